// round 2
// baseline (speedup 1.0000x reference)
#include <cuda_runtime.h>
#include <math.h>

#define WS_      14
#define NTOK     196      // WS*WS
#define NH_      12
#define HD_      64
#define DIM_     768
#define NWIN     200      // 8 * 5 * 5
#define BH_      2400     // NWIN * NH_
#define MROWS    39200    // NWIN * NTOK
#define IMGHW    64
#define QKV_N    2304

// ---- scratch (static device globals; no allocations allowed) ----
__device__ float g_q [BH_ * NTOK * HD_];   // [win*12+h][196][64]
__device__ float g_k [BH_ * NTOK * HD_];
__device__ float g_v [BH_ * NTOK * HD_];
__device__ float g_ao[MROWS * DIM_];       // attention out [win][tok][h*64+d]

// =====================================================================
// GEMM 1: qkv = gather(x) @ qkv_w^T + qkv_b   (M=39200, K=768, N=2304)
// =====================================================================
__global__ __launch_bounds__(256)
void qkv_gemm(const float* __restrict__ x, const float* __restrict__ w,
              const float* __restrict__ bias)
{
    __shared__ float As[16][132];
    __shared__ float Bs[16][132];
    const int tid = threadIdx.x;
    const int m0 = blockIdx.x * 128;
    const int n0 = blockIdx.y * 128;
    const int tx = tid & 15;
    const int ty = tid >> 4;

    int abase[2];
#pragma unroll
    for (int i = 0; i < 2; i++) {
        int lin = tid + 256 * i;
        int row = lin >> 2;
        int gm  = m0 + row;
        int base = -1;
        if (gm < MROWS) {
            int wdw = gm / NTOK, t = gm - wdw * NTOK;
            int b  = wdw / 25,  wi = wdw - b * 25;
            int wh = wi / 5,    ww = wi - wh * 5;
            int th = t / WS_,   tw = t - th * WS_;
            int y  = wh * WS_ + th;
            int xc = ww * WS_ + tw;
            if (y < IMGHW && xc < IMGHW)
                base = ((b * IMGHW + y) * IMGHW + xc) * DIM_;
        }
        abase[i] = base;
    }

    float acc[8][8];
#pragma unroll
    for (int i = 0; i < 8; i++)
#pragma unroll
        for (int j = 0; j < 8; j++) acc[i][j] = 0.f;

    for (int k0 = 0; k0 < DIM_; k0 += 16) {
#pragma unroll
        for (int i = 0; i < 2; i++) {
            int lin = tid + 256 * i;
            int row = lin >> 2;
            int kq  = (lin & 3) * 4;
            float4 v = make_float4(0.f, 0.f, 0.f, 0.f);
            if (abase[i] >= 0)
                v = *(const float4*)(x + abase[i] + k0 + kq);
            As[kq + 0][row] = v.x; As[kq + 1][row] = v.y;
            As[kq + 2][row] = v.z; As[kq + 3][row] = v.w;
        }
#pragma unroll
        for (int i = 0; i < 2; i++) {
            int lin = tid + 256 * i;
            int row = lin >> 2;
            int kq  = (lin & 3) * 4;
            float4 v = *(const float4*)(w + (n0 + row) * DIM_ + k0 + kq);
            Bs[kq + 0][row] = v.x; Bs[kq + 1][row] = v.y;
            Bs[kq + 2][row] = v.z; Bs[kq + 3][row] = v.w;
        }
        __syncthreads();
#pragma unroll
        for (int kk = 0; kk < 16; kk++) {
            float a[8], b[8];
            float4 t0 = *(const float4*)&As[kk][ty * 8];
            float4 t1 = *(const float4*)&As[kk][ty * 8 + 4];
            a[0]=t0.x; a[1]=t0.y; a[2]=t0.z; a[3]=t0.w;
            a[4]=t1.x; a[5]=t1.y; a[6]=t1.z; a[7]=t1.w;
            float4 u0 = *(const float4*)&Bs[kk][tx * 8];
            float4 u1 = *(const float4*)&Bs[kk][tx * 8 + 4];
            b[0]=u0.x; b[1]=u0.y; b[2]=u0.z; b[3]=u0.w;
            b[4]=u1.x; b[5]=u1.y; b[6]=u1.z; b[7]=u1.w;
#pragma unroll
            for (int i = 0; i < 8; i++)
#pragma unroll
                for (int j = 0; j < 8; j++)
                    acc[i][j] = fmaf(a[i], b[j], acc[i][j]);
        }
        __syncthreads();
    }

#pragma unroll
    for (int i = 0; i < 8; i++) {
        int gm = m0 + ty * 8 + i;
        if (gm >= MROWS) continue;
        int wdw = gm / NTOK, t = gm - wdw * NTOK;
#pragma unroll
        for (int j = 0; j < 8; j++) {
            int gn = n0 + tx * 8 + j;
            float c = acc[i][j] + bias[gn];
            int which = gn / DIM_;
            int r = gn - which * DIM_;
            int h = r >> 6, d = r & 63;
            int idx = ((wdw * NH_ + h) * NTOK + t) * HD_ + d;
            float* dst = (which == 0) ? g_q : ((which == 1) ? g_k : g_v);
            dst[idx] = c;
        }
    }
}

// =====================================================================
// Fused attention per (window, head).
// K stored TRANSPOSED in smem: kt[d][key], lane-consecutive float2 reads
// -> conflict-free (was 8-way conflicted). Q held in registers.
// =====================================================================
#define KT_STRIDE 202                      // even; staging write conflict <=2-way
#define NPAIR     98                       // 196 keys as float2 pairs
#define ATTN_SMEM_FLOATS (HD_*KT_STRIDE + NTOK*HD_ + 8*200 + 8*16 + 8*16)
#define ATTN_SMEM_BYTES  (ATTN_SMEM_FLOATS * 4)

__global__ __launch_bounds__(256, 2)
void attn_kernel(const float* __restrict__ rph, const float* __restrict__ rpw)
{
    extern __shared__ float sm[];
    float* kt  = sm;                          // [64][202]
    float* vs  = kt  + HD_ * KT_STRIDE;       // [196][64]
    float* ps  = vs  + NTOK * HD_;            // [8][200]
    float* rh  = ps  + 8 * 200;               // [8][16]
    float* rw  = rh  + 8 * 16;                // [8][16]

    const int bh   = blockIdx.x;
    const int tid  = threadIdx.x;
    const int lane = tid & 31;
    const int warp = tid >> 5;
    const float* q = g_q + bh * (NTOK * HD_);
    const float* k = g_k + bh * (NTOK * HD_);
    const float* v = g_v + bh * (NTOK * HD_);

    // stage K (transposed) and V
    for (int i = tid; i < NTOK * HD_; i += 256) {
        int j = i >> 6, d = i & 63;
        kt[d * KT_STRIDE + j] = k[i];
        vs[i] = v[i];
    }
    __syncthreads();

    const float scale = 0.125f;  // 64^-0.5
    float* rhw  = rh + warp * 16;
    float* rww  = rw + warp * 16;
    float* pw_f = ps + warp * 200;
    float2* pw2 = (float2*)pw_f;
    const float2* vs2 = (const float2*)vs;

    for (int qi = warp; qi < NTOK; qi += 8) {
        // ---- load q into registers (warp-uniform broadcast loads) ----
        float qarr[HD_];
        const float4* qg4 = (const float4*)(q + qi * HD_);
#pragma unroll
        for (int t = 0; t < 16; t++) {
            float4 f = __ldg(qg4 + t);
            qarr[4*t + 0] = f.x; qarr[4*t + 1] = f.y;
            qarr[4*t + 2] = f.z; qarr[4*t + 3] = f.w;
        }

        const int qh  = qi / WS_;
        const int qwc = qi - qh * WS_;

        // ---- rel-pos partial dots ----
        if (lane < WS_) {
            const float* r = rph + (qh - lane + WS_ - 1) * HD_;
            float s = 0.f;
#pragma unroll
            for (int d = 0; d < HD_; d++) s = fmaf(qarr[d], __ldg(r + d), s);
            rhw[lane] = s;
        } else if (lane >= 16 && lane < 16 + WS_) {
            int kw = lane - 16;
            const float* r = rpw + (qwc - kw + WS_ - 1) * HD_;
            float s = 0.f;
#pragma unroll
            for (int d = 0; d < HD_; d++) s = fmaf(qarr[d], __ldg(r + d), s);
            rww[kw] = s;
        }
        __syncwarp();

        // ---- scores: lane owns key pairs p = lane + 32c (p < 98) ----
        float a00=0.f,a01=0.f,a10=0.f,a11=0.f,a20=0.f,a21=0.f,a30=0.f,a31=0.f;
#pragma unroll 16
        for (int d = 0; d < HD_; d++) {
            float qd = qarr[d];
            const float2* kt2 = (const float2*)(kt + d * KT_STRIDE);
            float2 k0 = kt2[lane];
            float2 k1 = kt2[lane + 32];
            float2 k2 = kt2[lane + 64];
            a00 = fmaf(qd, k0.x, a00); a01 = fmaf(qd, k0.y, a01);
            a10 = fmaf(qd, k1.x, a10); a11 = fmaf(qd, k1.y, a11);
            a20 = fmaf(qd, k2.x, a20); a21 = fmaf(qd, k2.y, a21);
            if (lane < 2) {
                float2 k3 = kt2[lane + 96];
                a30 = fmaf(qd, k3.x, a30); a31 = fmaf(qd, k3.y, a31);
            }
        }

        float sc[8];
        float accs[8] = {a00,a01,a10,a11,a20,a21,a30,a31};
#pragma unroll
        for (int c = 0; c < 4; c++) {
            int p = lane + 32 * c;
#pragma unroll
            for (int e = 0; e < 2; e++) {
                int j = 2 * p + e;
                if (p < NPAIR) {
                    int kh = j / WS_, kwc = j - kh * WS_;
                    sc[2*c+e] = accs[2*c+e] * scale + rhw[kh] + rww[kwc];
                } else {
                    sc[2*c+e] = -INFINITY;
                }
            }
        }

        // ---- softmax over 196 keys (warp-wide) ----
        float mx = -INFINITY;
#pragma unroll
        for (int t = 0; t < 8; t++) mx = fmaxf(mx, sc[t]);
#pragma unroll
        for (int off = 16; off > 0; off >>= 1)
            mx = fmaxf(mx, __shfl_xor_sync(0xffffffffu, mx, off));
        float sum = 0.f;
#pragma unroll
        for (int c = 0; c < 4; c++) {
            int p = lane + 32 * c;
            if (p < NPAIR) {
                float p0 = __expf(sc[2*c+0] - mx);
                float p1 = __expf(sc[2*c+1] - mx);
                pw2[p] = make_float2(p0, p1);
                sum += p0 + p1;
            }
        }
#pragma unroll
        for (int off = 16; off > 0; off >>= 1)
            sum += __shfl_xor_sync(0xffffffffu, sum, off);
        __syncwarp();
        float inv = 1.f / sum;

        // ---- out[d] = sum_j p[j] * v[j][d];  lane owns d = 2*lane{,+1} ----
        float o0 = 0.f, o1 = 0.f;
#pragma unroll 4
        for (int j = 0; j < NTOK; j++) {
            float pj = pw_f[j];
            float2 vv = vs2[j * 32 + lane];
            o0 = fmaf(pj, vv.x, o0);
            o1 = fmaf(pj, vv.y, o1);
        }
        int wdw = bh / NH_, h = bh - wdw * NH_;
        float2* o = (float2*)(g_ao + (wdw * NTOK + qi) * DIM_ + h * HD_);
        o[lane] = make_float2(o0 * inv, o1 * inv);
        __syncwarp();
    }
}

// =====================================================================
// GEMM 2: out = g_ao @ proj_w^T + proj_b, scatter with un-partition+crop
// =====================================================================
__global__ __launch_bounds__(256)
void proj_gemm(const float* __restrict__ w, const float* __restrict__ bias,
               float* __restrict__ out)
{
    __shared__ float As[16][132];
    __shared__ float Bs[16][132];
    const int tid = threadIdx.x;
    const int m0 = blockIdx.x * 128;
    const int n0 = blockIdx.y * 128;
    const int tx = tid & 15;
    const int ty = tid >> 4;

    int abase[2];
#pragma unroll
    for (int i = 0; i < 2; i++) {
        int lin = tid + 256 * i;
        int row = lin >> 2;
        int gm  = m0 + row;
        abase[i] = (gm < MROWS) ? gm * DIM_ : -1;
    }

    float acc[8][8];
#pragma unroll
    for (int i = 0; i < 8; i++)
#pragma unroll
        for (int j = 0; j < 8; j++) acc[i][j] = 0.f;

    for (int k0 = 0; k0 < DIM_; k0 += 16) {
#pragma unroll
        for (int i = 0; i < 2; i++) {
            int lin = tid + 256 * i;
            int row = lin >> 2;
            int kq  = (lin & 3) * 4;
            float4 v = make_float4(0.f, 0.f, 0.f, 0.f);
            if (abase[i] >= 0)
                v = *(const float4*)(g_ao + abase[i] + k0 + kq);
            As[kq + 0][row] = v.x; As[kq + 1][row] = v.y;
            As[kq + 2][row] = v.z; As[kq + 3][row] = v.w;
        }
#pragma unroll
        for (int i = 0; i < 2; i++) {
            int lin = tid + 256 * i;
            int row = lin >> 2;
            int kq  = (lin & 3) * 4;
            float4 v = *(const float4*)(w + (n0 + row) * DIM_ + k0 + kq);
            Bs[kq + 0][row] = v.x; Bs[kq + 1][row] = v.y;
            Bs[kq + 2][row] = v.z; Bs[kq + 3][row] = v.w;
        }
        __syncthreads();
#pragma unroll
        for (int kk = 0; kk < 16; kk++) {
            float a[8], b[8];
            float4 t0 = *(const float4*)&As[kk][ty * 8];
            float4 t1 = *(const float4*)&As[kk][ty * 8 + 4];
            a[0]=t0.x; a[1]=t0.y; a[2]=t0.z; a[3]=t0.w;
            a[4]=t1.x; a[5]=t1.y; a[6]=t1.z; a[7]=t1.w;
            float4 u0 = *(const float4*)&Bs[kk][tx * 8];
            float4 u1 = *(const float4*)&Bs[kk][tx * 8 + 4];
            b[0]=u0.x; b[1]=u0.y; b[2]=u0.z; b[3]=u0.w;
            b[4]=u1.x; b[5]=u1.y; b[6]=u1.z; b[7]=u1.w;
#pragma unroll
            for (int i = 0; i < 8; i++)
#pragma unroll
                for (int j = 0; j < 8; j++)
                    acc[i][j] = fmaf(a[i], b[j], acc[i][j]);
        }
        __syncthreads();
    }

#pragma unroll
    for (int i = 0; i < 8; i++) {
        int gm = m0 + ty * 8 + i;
        if (gm >= MROWS) continue;
        int wdw = gm / NTOK, t = gm - wdw * NTOK;
        int b  = wdw / 25,  wi = wdw - b * 25;
        int wh = wi / 5,    ww = wi - wh * 5;
        int th = t / WS_,   tw = t - th * WS_;
        int y  = wh * WS_ + th;
        int xc = ww * WS_ + tw;
        if (y >= IMGHW || xc >= IMGHW) continue;
        float* orow = out + ((b * IMGHW + y) * IMGHW + xc) * DIM_;
#pragma unroll
        for (int j = 0; j < 8; j++) {
            int gn = n0 + tx * 8 + j;
            orow[gn] = acc[i][j] + bias[gn];
        }
    }
}

// =====================================================================
extern "C" void kernel_launch(void* const* d_in, const int* in_sizes, int n_in,
                              void* d_out, int out_size)
{
    const float* x      = (const float*)d_in[0];
    const float* qkv_w  = (const float*)d_in[1];
    const float* qkv_b  = (const float*)d_in[2];
    const float* proj_w = (const float*)d_in[3];
    const float* proj_b = (const float*)d_in[4];
    const float* rph    = (const float*)d_in[5];
    const float* rpw    = (const float*)d_in[6];
    float* out = (float*)d_out;

    cudaFuncSetAttribute(attn_kernel,
                         cudaFuncAttributeMaxDynamicSharedMemorySize,
                         ATTN_SMEM_BYTES);

    dim3 g1((MROWS + 127) / 128, QKV_N / 128);
    qkv_gemm<<<g1, 256>>>(x, qkv_w, qkv_b);

    attn_kernel<<<BH_, 256, ATTN_SMEM_BYTES>>>(rph, rpw);

    dim3 g2((MROWS + 127) / 128, DIM_ / 128);
    proj_gemm<<<g2, 256>>>(proj_w, proj_b, out);
}

// round 3
// speedup vs baseline: 1.1103x; 1.1103x over previous
#include <cuda_runtime.h>
#include <math.h>

#define WS_      14
#define NTOK     196      // WS*WS
#define NH_      12
#define HD_      64
#define DIM_     768
#define NWIN     200      // 8 * 5 * 5
#define BH_      2400     // NWIN * NH_
#define MROWS    39200    // NWIN * NTOK
#define IMGHW    64
#define QKV_N    2304

// ---- scratch (static device globals; no allocations allowed) ----
__device__ float g_q [BH_ * NTOK * HD_];   // [win*12+h][196][64]
__device__ float g_k [BH_ * NTOK * HD_];
__device__ float g_v [BH_ * NTOK * HD_];
__device__ float g_ao[MROWS * DIM_];       // attention out [win][tok][h*64+d]

// =====================================================================
// GEMM 1: qkv = gather(x) @ qkv_w^T + qkv_b   (M=39200, K=768, N=2304)
// =====================================================================
__global__ __launch_bounds__(256)
void qkv_gemm(const float* __restrict__ x, const float* __restrict__ w,
              const float* __restrict__ bias)
{
    __shared__ float As[16][132];
    __shared__ float Bs[16][132];
    const int tid = threadIdx.x;
    const int m0 = blockIdx.x * 128;
    const int n0 = blockIdx.y * 128;
    const int tx = tid & 15;
    const int ty = tid >> 4;

    int abase[2];
#pragma unroll
    for (int i = 0; i < 2; i++) {
        int lin = tid + 256 * i;
        int row = lin >> 2;
        int gm  = m0 + row;
        int base = -1;
        if (gm < MROWS) {
            int wdw = gm / NTOK, t = gm - wdw * NTOK;
            int b  = wdw / 25,  wi = wdw - b * 25;
            int wh = wi / 5,    ww = wi - wh * 5;
            int th = t / WS_,   tw = t - th * WS_;
            int y  = wh * WS_ + th;
            int xc = ww * WS_ + tw;
            if (y < IMGHW && xc < IMGHW)
                base = ((b * IMGHW + y) * IMGHW + xc) * DIM_;
        }
        abase[i] = base;
    }

    float acc[8][8];
#pragma unroll
    for (int i = 0; i < 8; i++)
#pragma unroll
        for (int j = 0; j < 8; j++) acc[i][j] = 0.f;

    for (int k0 = 0; k0 < DIM_; k0 += 16) {
#pragma unroll
        for (int i = 0; i < 2; i++) {
            int lin = tid + 256 * i;
            int row = lin >> 2;
            int kq  = (lin & 3) * 4;
            float4 v = make_float4(0.f, 0.f, 0.f, 0.f);
            if (abase[i] >= 0)
                v = *(const float4*)(x + abase[i] + k0 + kq);
            As[kq + 0][row] = v.x; As[kq + 1][row] = v.y;
            As[kq + 2][row] = v.z; As[kq + 3][row] = v.w;
        }
#pragma unroll
        for (int i = 0; i < 2; i++) {
            int lin = tid + 256 * i;
            int row = lin >> 2;
            int kq  = (lin & 3) * 4;
            float4 v = *(const float4*)(w + (n0 + row) * DIM_ + k0 + kq);
            Bs[kq + 0][row] = v.x; Bs[kq + 1][row] = v.y;
            Bs[kq + 2][row] = v.z; Bs[kq + 3][row] = v.w;
        }
        __syncthreads();
#pragma unroll
        for (int kk = 0; kk < 16; kk++) {
            float a[8], b[8];
            float4 t0 = *(const float4*)&As[kk][ty * 8];
            float4 t1 = *(const float4*)&As[kk][ty * 8 + 4];
            a[0]=t0.x; a[1]=t0.y; a[2]=t0.z; a[3]=t0.w;
            a[4]=t1.x; a[5]=t1.y; a[6]=t1.z; a[7]=t1.w;
            float4 u0 = *(const float4*)&Bs[kk][tx * 8];
            float4 u1 = *(const float4*)&Bs[kk][tx * 8 + 4];
            b[0]=u0.x; b[1]=u0.y; b[2]=u0.z; b[3]=u0.w;
            b[4]=u1.x; b[5]=u1.y; b[6]=u1.z; b[7]=u1.w;
#pragma unroll
            for (int i = 0; i < 8; i++)
#pragma unroll
                for (int j = 0; j < 8; j++)
                    acc[i][j] = fmaf(a[i], b[j], acc[i][j]);
        }
        __syncthreads();
    }

#pragma unroll
    for (int i = 0; i < 8; i++) {
        int gm = m0 + ty * 8 + i;
        if (gm >= MROWS) continue;
        int wdw = gm / NTOK, t = gm - wdw * NTOK;
#pragma unroll
        for (int j = 0; j < 8; j++) {
            int gn = n0 + tx * 8 + j;
            float c = acc[i][j] + bias[gn];
            int which = gn / DIM_;
            int r = gn - which * DIM_;
            int h = r >> 6, d = r & 63;
            int idx = ((wdw * NH_ + h) * NTOK + t) * HD_ + d;
            float* dst = (which == 0) ? g_q : ((which == 1) ? g_k : g_v);
            dst[idx] = c;
        }
    }
}

// =====================================================================
// Fused attention per (window, head), 512 threads, 16 warps.
// Each warp processes 4 queries at once: K/V smem reads amortized 4x.
//   kt[d][key]   transposed K, conflict-free float2 reads
//   vs[key][d]   V, float2 reads (2-way)
//   pv[key]      float4 = probs of the 4 in-flight queries (bcast read)
//   q in smem (broadcast), NO per-thread q array -> no spill.
// =====================================================================
#define KT_STRIDE 198
#define ATTN_SMEM_FLOATS (HD_*KT_STRIDE + NTOK*HD_ + 16*256 + 16*784 + 16*64 + 16*64)
#define ATTN_SMEM_BYTES  (ATTN_SMEM_FLOATS * 4)

__global__ __launch_bounds__(512, 1)
void attn_kernel(const float* __restrict__ rph, const float* __restrict__ rpw)
{
    extern __shared__ float sm[];
    float* kt = sm;                        // [64][198]
    float* vs = kt + HD_ * KT_STRIDE;      // [196][64]
    float* qs = vs + NTOK * HD_;           // [16][4][64]
    float* pv = qs + 16 * 256;             // [16][196*4]
    float* rh = pv + 16 * 784;             // [16][4*16]
    float* rw = rh + 16 * 64;              // [16][4*16]

    const int bh   = blockIdx.x;
    const int tid  = threadIdx.x;
    const int lane = tid & 31;
    const int warp = tid >> 5;
    const float* q = g_q + bh * (NTOK * HD_);
    const float* k = g_k + bh * (NTOK * HD_);
    const float* v = g_v + bh * (NTOK * HD_);

    // stage K (transposed) and V
    for (int i = tid; i < NTOK * HD_; i += 512) {
        int j = i >> 6, d = i & 63;
        kt[d * KT_STRIDE + j] = k[i];
        vs[i] = v[i];
    }
    __syncthreads();

    const float scale = 0.125f;  // 64^-0.5
    float*  qw  = qs + warp * 256;
    float2* qw2 = (float2*)qw;
    float4* pw4 = (float4*)(pv + warp * 784);
    float*  rhw = rh + warp * 64;
    float*  rww = rw + warp * 64;
    const float2* vs2 = (const float2*)vs;
    const int wdw = bh / NH_, hh = bh - wdw * NH_;

    // key -> (kh, kw) for this lane's 8 candidate keys
    int khs[8], kws[8];
#pragma unroll
    for (int c = 0; c < 4; c++) {
#pragma unroll
        for (int e = 0; e < 2; e++) {
            int j = 2 * (lane + 32 * c) + e;
            if (j < NTOK) { khs[2*c+e] = j / WS_; kws[2*c+e] = j - (j / WS_) * WS_; }
            else          { khs[2*c+e] = 0;       kws[2*c+e] = 0; }
        }
    }

    for (int pass = 0; pass < 4; pass++) {
        int qbase = pass * 64 + warp * 4;
        if (qbase >= NTOK) break;            // per-warp exit; no block barriers below

        // ---- stage 4 q rows into smem (coalesced) ----
        const float2* qg2 = (const float2*)(q + qbase * HD_);
#pragma unroll
        for (int t = 0; t < 4; t++) qw2[lane + 32 * t] = qg2[lane + 32 * t];
        __syncwarp();

        // ---- rel-pos partial dots for 4 queries (4-wide ILP chains) ----
        if (lane < WS_) {
            const float* r0 = rph + ((qbase+0) / WS_ - lane + WS_ - 1) * HD_;
            const float* r1 = rph + ((qbase+1) / WS_ - lane + WS_ - 1) * HD_;
            const float* r2 = rph + ((qbase+2) / WS_ - lane + WS_ - 1) * HD_;
            const float* r3 = rph + ((qbase+3) / WS_ - lane + WS_ - 1) * HD_;
            float s0=0.f, s1=0.f, s2=0.f, s3=0.f;
#pragma unroll
            for (int d = 0; d < HD_; d++) {
                s0 = fmaf(qw[d],       __ldg(r0 + d), s0);
                s1 = fmaf(qw[64 + d],  __ldg(r1 + d), s1);
                s2 = fmaf(qw[128 + d], __ldg(r2 + d), s2);
                s3 = fmaf(qw[192 + d], __ldg(r3 + d), s3);
            }
            rhw[0*16+lane]=s0; rhw[1*16+lane]=s1; rhw[2*16+lane]=s2; rhw[3*16+lane]=s3;
        } else if (lane >= 16 && lane < 16 + WS_) {
            int kw = lane - 16;
            int w0=(qbase+0)%WS_, w1=(qbase+1)%WS_, w2=(qbase+2)%WS_, w3=(qbase+3)%WS_;
            const float* r0 = rpw + (w0 - kw + WS_ - 1) * HD_;
            const float* r1 = rpw + (w1 - kw + WS_ - 1) * HD_;
            const float* r2 = rpw + (w2 - kw + WS_ - 1) * HD_;
            const float* r3 = rpw + (w3 - kw + WS_ - 1) * HD_;
            float s0=0.f, s1=0.f, s2=0.f, s3=0.f;
#pragma unroll
            for (int d = 0; d < HD_; d++) {
                s0 = fmaf(qw[d],       __ldg(r0 + d), s0);
                s1 = fmaf(qw[64 + d],  __ldg(r1 + d), s1);
                s2 = fmaf(qw[128 + d], __ldg(r2 + d), s2);
                s3 = fmaf(qw[192 + d], __ldg(r3 + d), s3);
            }
            rww[0*16+kw]=s0; rww[1*16+kw]=s1; rww[2*16+kw]=s2; rww[3*16+kw]=s3;
        }
        __syncwarp();

        // ---- scores: 4 queries x 8 key-slots per lane ----
        float acc[4][8];
#pragma unroll
        for (int u = 0; u < 4; u++)
#pragma unroll
            for (int t = 0; t < 8; t++) acc[u][t] = 0.f;

#pragma unroll 4
        for (int d = 0; d < HD_; d++) {
            const float2* kt2 = (const float2*)(kt + d * KT_STRIDE);
            float2 k0 = kt2[lane];
            float2 k1 = kt2[lane + 32];
            float2 k2 = kt2[lane + 64];
            float q0 = qw[d], q1 = qw[64 + d], q2 = qw[128 + d], q3 = qw[192 + d];
            acc[0][0]=fmaf(q0,k0.x,acc[0][0]); acc[0][1]=fmaf(q0,k0.y,acc[0][1]);
            acc[0][2]=fmaf(q0,k1.x,acc[0][2]); acc[0][3]=fmaf(q0,k1.y,acc[0][3]);
            acc[0][4]=fmaf(q0,k2.x,acc[0][4]); acc[0][5]=fmaf(q0,k2.y,acc[0][5]);
            acc[1][0]=fmaf(q1,k0.x,acc[1][0]); acc[1][1]=fmaf(q1,k0.y,acc[1][1]);
            acc[1][2]=fmaf(q1,k1.x,acc[1][2]); acc[1][3]=fmaf(q1,k1.y,acc[1][3]);
            acc[1][4]=fmaf(q1,k2.x,acc[1][4]); acc[1][5]=fmaf(q1,k2.y,acc[1][5]);
            acc[2][0]=fmaf(q2,k0.x,acc[2][0]); acc[2][1]=fmaf(q2,k0.y,acc[2][1]);
            acc[2][2]=fmaf(q2,k1.x,acc[2][2]); acc[2][3]=fmaf(q2,k1.y,acc[2][3]);
            acc[2][4]=fmaf(q2,k2.x,acc[2][4]); acc[2][5]=fmaf(q2,k2.y,acc[2][5]);
            acc[3][0]=fmaf(q3,k0.x,acc[3][0]); acc[3][1]=fmaf(q3,k0.y,acc[3][1]);
            acc[3][2]=fmaf(q3,k1.x,acc[3][2]); acc[3][3]=fmaf(q3,k1.y,acc[3][3]);
            acc[3][4]=fmaf(q3,k2.x,acc[3][4]); acc[3][5]=fmaf(q3,k2.y,acc[3][5]);
            if (lane < 2) {
                float2 k3 = kt2[lane + 96];
                acc[0][6]=fmaf(q0,k3.x,acc[0][6]); acc[0][7]=fmaf(q0,k3.y,acc[0][7]);
                acc[1][6]=fmaf(q1,k3.x,acc[1][6]); acc[1][7]=fmaf(q1,k3.y,acc[1][7]);
                acc[2][6]=fmaf(q2,k3.x,acc[2][6]); acc[2][7]=fmaf(q2,k3.y,acc[2][7]);
                acc[3][6]=fmaf(q3,k3.x,acc[3][6]); acc[3][7]=fmaf(q3,k3.y,acc[3][7]);
            }
        }

        // ---- softmax per query + pack probs as float4 per key ----
        float inv[4];
        float ex[4][8];
#pragma unroll
        for (int u = 0; u < 4; u++) {
            float sc[8];
#pragma unroll
            for (int c = 0; c < 4; c++) {
                int p = lane + 32 * c;
#pragma unroll
                for (int e = 0; e < 2; e++) {
                    int t = 2 * c + e;
                    sc[t] = (p < 98)
                        ? acc[u][t] * scale + rhw[u*16 + khs[t]] + rww[u*16 + kws[t]]
                        : -INFINITY;
                }
            }
            float mx = -INFINITY;
#pragma unroll
            for (int t = 0; t < 8; t++) mx = fmaxf(mx, sc[t]);
#pragma unroll
            for (int off = 16; off > 0; off >>= 1)
                mx = fmaxf(mx, __shfl_xor_sync(0xffffffffu, mx, off));
            float sum = 0.f;
#pragma unroll
            for (int c = 0; c < 4; c++) {
                int p = lane + 32 * c;
#pragma unroll
                for (int e = 0; e < 2; e++) {
                    int t = 2 * c + e;
                    float pe = (p < 98) ? __expf(sc[t] - mx) : 0.f;
                    ex[u][t] = pe;
                    sum += pe;
                }
            }
#pragma unroll
            for (int off = 16; off > 0; off >>= 1)
                sum += __shfl_xor_sync(0xffffffffu, sum, off);
            inv[u] = 1.f / sum;
        }
#pragma unroll
        for (int c = 0; c < 4; c++) {
            int p = lane + 32 * c;
            if (p < 98) {
                pw4[2*p]   = make_float4(ex[0][2*c],   ex[1][2*c],   ex[2][2*c],   ex[3][2*c]);
                pw4[2*p+1] = make_float4(ex[0][2*c+1], ex[1][2*c+1], ex[2][2*c+1], ex[3][2*c+1]);
            }
        }
        __syncwarp();

        // ---- AV: lane owns dims 2*lane, 2*lane+1 for all 4 queries ----
        float o00=0.f,o01=0.f,o10=0.f,o11=0.f,o20=0.f,o21=0.f,o30=0.f,o31=0.f;
#pragma unroll 2
        for (int j = 0; j < NTOK; j++) {
            float4 pj = pw4[j];
            float2 vv = vs2[j * 32 + lane];
            o00 = fmaf(pj.x, vv.x, o00); o01 = fmaf(pj.x, vv.y, o01);
            o10 = fmaf(pj.y, vv.x, o10); o11 = fmaf(pj.y, vv.y, o11);
            o20 = fmaf(pj.z, vv.x, o20); o21 = fmaf(pj.z, vv.y, o21);
            o30 = fmaf(pj.w, vv.x, o30); o31 = fmaf(pj.w, vv.y, o31);
        }
        {
            float2* o0 = (float2*)(g_ao + (wdw * NTOK + qbase + 0) * DIM_ + hh * HD_);
            float2* o1 = (float2*)(g_ao + (wdw * NTOK + qbase + 1) * DIM_ + hh * HD_);
            float2* o2 = (float2*)(g_ao + (wdw * NTOK + qbase + 2) * DIM_ + hh * HD_);
            float2* o3 = (float2*)(g_ao + (wdw * NTOK + qbase + 3) * DIM_ + hh * HD_);
            o0[lane] = make_float2(o00 * inv[0], o01 * inv[0]);
            o1[lane] = make_float2(o10 * inv[1], o11 * inv[1]);
            o2[lane] = make_float2(o20 * inv[2], o21 * inv[2]);
            o3[lane] = make_float2(o30 * inv[3], o31 * inv[3]);
        }
        __syncwarp();
    }
}

// =====================================================================
// GEMM 2: out = g_ao @ proj_w^T + proj_b, scatter with un-partition+crop
// =====================================================================
__global__ __launch_bounds__(256)
void proj_gemm(const float* __restrict__ w, const float* __restrict__ bias,
               float* __restrict__ out)
{
    __shared__ float As[16][132];
    __shared__ float Bs[16][132];
    const int tid = threadIdx.x;
    const int m0 = blockIdx.x * 128;
    const int n0 = blockIdx.y * 128;
    const int tx = tid & 15;
    const int ty = tid >> 4;

    int abase[2];
#pragma unroll
    for (int i = 0; i < 2; i++) {
        int lin = tid + 256 * i;
        int row = lin >> 2;
        int gm  = m0 + row;
        abase[i] = (gm < MROWS) ? gm * DIM_ : -1;
    }

    float acc[8][8];
#pragma unroll
    for (int i = 0; i < 8; i++)
#pragma unroll
        for (int j = 0; j < 8; j++) acc[i][j] = 0.f;

    for (int k0 = 0; k0 < DIM_; k0 += 16) {
#pragma unroll
        for (int i = 0; i < 2; i++) {
            int lin = tid + 256 * i;
            int row = lin >> 2;
            int kq  = (lin & 3) * 4;
            float4 v = make_float4(0.f, 0.f, 0.f, 0.f);
            if (abase[i] >= 0)
                v = *(const float4*)(g_ao + abase[i] + k0 + kq);
            As[kq + 0][row] = v.x; As[kq + 1][row] = v.y;
            As[kq + 2][row] = v.z; As[kq + 3][row] = v.w;
        }
#pragma unroll
        for (int i = 0; i < 2; i++) {
            int lin = tid + 256 * i;
            int row = lin >> 2;
            int kq  = (lin & 3) * 4;
            float4 v = *(const float4*)(w + (n0 + row) * DIM_ + k0 + kq);
            Bs[kq + 0][row] = v.x; Bs[kq + 1][row] = v.y;
            Bs[kq + 2][row] = v.z; Bs[kq + 3][row] = v.w;
        }
        __syncthreads();
#pragma unroll
        for (int kk = 0; kk < 16; kk++) {
            float a[8], b[8];
            float4 t0 = *(const float4*)&As[kk][ty * 8];
            float4 t1 = *(const float4*)&As[kk][ty * 8 + 4];
            a[0]=t0.x; a[1]=t0.y; a[2]=t0.z; a[3]=t0.w;
            a[4]=t1.x; a[5]=t1.y; a[6]=t1.z; a[7]=t1.w;
            float4 u0 = *(const float4*)&Bs[kk][tx * 8];
            float4 u1 = *(const float4*)&Bs[kk][tx * 8 + 4];
            b[0]=u0.x; b[1]=u0.y; b[2]=u0.z; b[3]=u0.w;
            b[4]=u1.x; b[5]=u1.y; b[6]=u1.z; b[7]=u1.w;
#pragma unroll
            for (int i = 0; i < 8; i++)
#pragma unroll
                for (int j = 0; j < 8; j++)
                    acc[i][j] = fmaf(a[i], b[j], acc[i][j]);
        }
        __syncthreads();
    }

#pragma unroll
    for (int i = 0; i < 8; i++) {
        int gm = m0 + ty * 8 + i;
        if (gm >= MROWS) continue;
        int wdw = gm / NTOK, t = gm - wdw * NTOK;
        int b  = wdw / 25,  wi = wdw - b * 25;
        int wh = wi / 5,    ww = wi - wh * 5;
        int th = t / WS_,   tw = t - th * WS_;
        int y  = wh * WS_ + th;
        int xc = ww * WS_ + tw;
        if (y >= IMGHW || xc >= IMGHW) continue;
        float* orow = out + ((b * IMGHW + y) * IMGHW + xc) * DIM_;
#pragma unroll
        for (int j = 0; j < 8; j++) {
            int gn = n0 + tx * 8 + j;
            orow[gn] = acc[i][j] + bias[gn];
        }
    }
}

// =====================================================================
extern "C" void kernel_launch(void* const* d_in, const int* in_sizes, int n_in,
                              void* d_out, int out_size)
{
    const float* x      = (const float*)d_in[0];
    const float* qkv_w  = (const float*)d_in[1];
    const float* qkv_b  = (const float*)d_in[2];
    const float* proj_w = (const float*)d_in[3];
    const float* proj_b = (const float*)d_in[4];
    const float* rph    = (const float*)d_in[5];
    const float* rpw    = (const float*)d_in[6];
    float* out = (float*)d_out;

    cudaFuncSetAttribute(attn_kernel,
                         cudaFuncAttributeMaxDynamicSharedMemorySize,
                         ATTN_SMEM_BYTES);

    dim3 g1((MROWS + 127) / 128, QKV_N / 128);
    qkv_gemm<<<g1, 256>>>(x, qkv_w, qkv_b);

    attn_kernel<<<BH_, 512, ATTN_SMEM_BYTES>>>(rph, rpw);

    dim3 g2((MROWS + 127) / 128, DIM_ / 128);
    proj_gemm<<<g2, 256>>>(proj_w, proj_b, out);
}

// round 10
// speedup vs baseline: 1.1308x; 1.0184x over previous
#include <cuda_runtime.h>
#include <math.h>

#define WS_      14
#define NTOK     196
#define NH_      12
#define HD_      64
#define DIM_     768
#define NWIN     200
#define BH_      2400
#define MROWS    39200
#define IMGHW    64
#define QKV_N    2304

// ---- scratch ----
__device__ float g_q [BH_ * NTOK * HD_];
__device__ float g_k [BH_ * NTOK * HD_];
__device__ float g_v [BH_ * NTOK * HD_];
__device__ float g_ao[MROWS * DIM_];

// =====================================================================
// GEMM 1: qkv = gather(x) @ qkv_w^T + qkv_b   (M=39200, K=768, N=2304)
// Double-buffered: prefetch K-tile c+1 into regs, compute tile c,
// then STS -> other buffer.  16 extra regs only.
// =====================================================================
__global__ __launch_bounds__(256)
void qkv_gemm(const float* __restrict__ x, const float* __restrict__ w,
              const float* __restrict__ bias)
{
    __shared__ float As[2][16][132];
    __shared__ float Bs[2][16][132];
    const int tid = threadIdx.x;
    const int m0 = blockIdx.x * 128;
    const int n0 = blockIdx.y * 128;
    const int tx = tid & 15;
    const int ty = tid >> 4;

    int abase[2];
#pragma unroll
    for (int i = 0; i < 2; i++) {
        int lin = tid + 256 * i;
        int row = lin >> 2;
        int gm  = m0 + row;
        int base = -1;
        if (gm < MROWS) {
            int wdw = gm / NTOK, t = gm - wdw * NTOK;
            int b  = wdw / 25,  wi = wdw - b * 25;
            int wh = wi / 5,    ww = wi - wh * 5;
            int th = t / WS_,   tw = t - th * WS_;
            int y  = wh * WS_ + th;
            int xc = ww * WS_ + tw;
            if (y < IMGHW && xc < IMGHW)
                base = ((b * IMGHW + y) * IMGHW + xc) * DIM_;
        }
        abase[i] = base;
    }

    float acc[8][8];
#pragma unroll
    for (int i = 0; i < 8; i++)
#pragma unroll
        for (int j = 0; j < 8; j++) acc[i][j] = 0.f;

    float4 pa[2], pb[2];

    // prologue: stage 0 -> regs -> buf 0
#pragma unroll
    for (int i = 0; i < 2; i++) {
        int lin = tid + 256 * i;
        int kq  = (lin & 3) * 4;
        pa[i] = make_float4(0.f, 0.f, 0.f, 0.f);
        if (abase[i] >= 0) pa[i] = *(const float4*)(x + abase[i] + kq);
        int row = lin >> 2;
        pb[i] = *(const float4*)(w + (n0 + row) * DIM_ + kq);
    }
#pragma unroll
    for (int i = 0; i < 2; i++) {
        int lin = tid + 256 * i;
        int row = lin >> 2;
        int kq  = (lin & 3) * 4;
        As[0][kq + 0][row] = pa[i].x; As[0][kq + 1][row] = pa[i].y;
        As[0][kq + 2][row] = pa[i].z; As[0][kq + 3][row] = pa[i].w;
        Bs[0][kq + 0][row] = pb[i].x; Bs[0][kq + 1][row] = pb[i].y;
        Bs[0][kq + 2][row] = pb[i].z; Bs[0][kq + 3][row] = pb[i].w;
    }
    __syncthreads();

    const int NK = DIM_ / 16;   // 48
    for (int c = 0; c < NK; c++) {
        // prefetch next tile into regs (latency hidden by compute below)
        if (c + 1 < NK) {
            int k0 = (c + 1) * 16;
#pragma unroll
            for (int i = 0; i < 2; i++) {
                int lin = tid + 256 * i;
                int kq  = (lin & 3) * 4;
                pa[i] = make_float4(0.f, 0.f, 0.f, 0.f);
                if (abase[i] >= 0) pa[i] = *(const float4*)(x + abase[i] + k0 + kq);
                int row = lin >> 2;
                pb[i] = *(const float4*)(w + (n0 + row) * DIM_ + k0 + kq);
            }
        }

        const int buf = c & 1;
#pragma unroll
        for (int kk = 0; kk < 16; kk++) {
            float a[8], b[8];
            float4 t0 = *(const float4*)&As[buf][kk][ty * 8];
            float4 t1 = *(const float4*)&As[buf][kk][ty * 8 + 4];
            a[0]=t0.x; a[1]=t0.y; a[2]=t0.z; a[3]=t0.w;
            a[4]=t1.x; a[5]=t1.y; a[6]=t1.z; a[7]=t1.w;
            float4 u0 = *(const float4*)&Bs[buf][kk][tx * 8];
            float4 u1 = *(const float4*)&Bs[buf][kk][tx * 8 + 4];
            b[0]=u0.x; b[1]=u0.y; b[2]=u0.z; b[3]=u0.w;
            b[4]=u1.x; b[5]=u1.y; b[6]=u1.z; b[7]=u1.w;
#pragma unroll
            for (int i = 0; i < 8; i++)
#pragma unroll
                for (int j = 0; j < 8; j++)
                    acc[i][j] = fmaf(a[i], b[j], acc[i][j]);
        }

        if (c + 1 < NK) {
            const int nb = (c + 1) & 1;
#pragma unroll
            for (int i = 0; i < 2; i++) {
                int lin = tid + 256 * i;
                int row = lin >> 2;
                int kq  = (lin & 3) * 4;
                As[nb][kq + 0][row] = pa[i].x; As[nb][kq + 1][row] = pa[i].y;
                As[nb][kq + 2][row] = pa[i].z; As[nb][kq + 3][row] = pa[i].w;
                Bs[nb][kq + 0][row] = pb[i].x; Bs[nb][kq + 1][row] = pb[i].y;
                Bs[nb][kq + 2][row] = pb[i].z; Bs[nb][kq + 3][row] = pb[i].w;
            }
        }
        __syncthreads();
    }

#pragma unroll
    for (int i = 0; i < 8; i++) {
        int gm = m0 + ty * 8 + i;
        if (gm >= MROWS) continue;
        int wdw = gm / NTOK, t = gm - wdw * NTOK;
#pragma unroll
        for (int j = 0; j < 8; j++) {
            int gn = n0 + tx * 8 + j;
            float c = acc[i][j] + bias[gn];
            int which = gn / DIM_;
            int r = gn - which * DIM_;
            int h = r >> 6, d = r & 63;
            int idx = ((wdw * NH_ + h) * NTOK + t) * HD_ + d;
            float* dst = (which == 0) ? g_q : ((which == 1) ? g_k : g_v);
            dst[idx] = c;
        }
    }
}

// =====================================================================
// Fused attention (round-3 version, byte-identical — known passing)
// =====================================================================
#define KT_STRIDE 198
#define ATTN_SMEM_FLOATS (HD_*KT_STRIDE + NTOK*HD_ + 16*256 + 16*784 + 16*64 + 16*64)
#define ATTN_SMEM_BYTES  (ATTN_SMEM_FLOATS * 4)

__global__ __launch_bounds__(512, 1)
void attn_kernel(const float* __restrict__ rph, const float* __restrict__ rpw)
{
    extern __shared__ float sm[];
    float* kt = sm;
    float* vs = kt + HD_ * KT_STRIDE;
    float* qs = vs + NTOK * HD_;
    float* pv = qs + 16 * 256;
    float* rh = pv + 16 * 784;
    float* rw = rh + 16 * 64;

    const int bh   = blockIdx.x;
    const int tid  = threadIdx.x;
    const int lane = tid & 31;
    const int warp = tid >> 5;
    const float* q = g_q + bh * (NTOK * HD_);
    const float* k = g_k + bh * (NTOK * HD_);
    const float* v = g_v + bh * (NTOK * HD_);

    for (int i = tid; i < NTOK * HD_; i += 512) {
        int j = i >> 6, d = i & 63;
        kt[d * KT_STRIDE + j] = k[i];
        vs[i] = v[i];
    }
    __syncthreads();

    const float scale = 0.125f;
    float*  qw  = qs + warp * 256;
    float2* qw2 = (float2*)qw;
    float4* pw4 = (float4*)(pv + warp * 784);
    float*  rhw = rh + warp * 64;
    float*  rww = rw + warp * 64;
    const float2* vs2 = (const float2*)vs;
    const int wdw = bh / NH_, hh = bh - wdw * NH_;

    int khs[8], kws[8];
#pragma unroll
    for (int c = 0; c < 4; c++)
#pragma unroll
        for (int e = 0; e < 2; e++) {
            int j = 2 * (lane + 32 * c) + e;
            if (j < NTOK) { khs[2*c+e] = j / WS_; kws[2*c+e] = j - (j / WS_) * WS_; }
            else          { khs[2*c+e] = 0;       kws[2*c+e] = 0; }
        }

    for (int pass = 0; pass < 4; pass++) {
        int qbase = pass * 64 + warp * 4;
        if (qbase >= NTOK) break;

        const float2* qg2 = (const float2*)(q + qbase * HD_);
#pragma unroll
        for (int t = 0; t < 4; t++) qw2[lane + 32 * t] = qg2[lane + 32 * t];
        __syncwarp();

        if (lane < WS_) {
            const float* r0 = rph + ((qbase+0) / WS_ - lane + WS_ - 1) * HD_;
            const float* r1 = rph + ((qbase+1) / WS_ - lane + WS_ - 1) * HD_;
            const float* r2 = rph + ((qbase+2) / WS_ - lane + WS_ - 1) * HD_;
            const float* r3 = rph + ((qbase+3) / WS_ - lane + WS_ - 1) * HD_;
            float s0=0.f, s1=0.f, s2=0.f, s3=0.f;
#pragma unroll
            for (int d = 0; d < HD_; d++) {
                s0 = fmaf(qw[d],       __ldg(r0 + d), s0);
                s1 = fmaf(qw[64 + d],  __ldg(r1 + d), s1);
                s2 = fmaf(qw[128 + d], __ldg(r2 + d), s2);
                s3 = fmaf(qw[192 + d], __ldg(r3 + d), s3);
            }
            rhw[0*16+lane]=s0; rhw[1*16+lane]=s1; rhw[2*16+lane]=s2; rhw[3*16+lane]=s3;
        } else if (lane >= 16 && lane < 16 + WS_) {
            int kw = lane - 16;
            int w0=(qbase+0)%WS_, w1=(qbase+1)%WS_, w2=(qbase+2)%WS_, w3=(qbase+3)%WS_;
            const float* r0 = rpw + (w0 - kw + WS_ - 1) * HD_;
            const float* r1 = rpw + (w1 - kw + WS_ - 1) * HD_;
            const float* r2 = rpw + (w2 - kw + WS_ - 1) * HD_;
            const float* r3 = rpw + (w3 - kw + WS_ - 1) * HD_;
            float s0=0.f, s1=0.f, s2=0.f, s3=0.f;
#pragma unroll
            for (int d = 0; d < HD_; d++) {
                s0 = fmaf(qw[d],       __ldg(r0 + d), s0);
                s1 = fmaf(qw[64 + d],  __ldg(r1 + d), s1);
                s2 = fmaf(qw[128 + d], __ldg(r2 + d), s2);
                s3 = fmaf(qw[192 + d], __ldg(r3 + d), s3);
            }
            rww[0*16+kw]=s0; rww[1*16+kw]=s1; rww[2*16+kw]=s2; rww[3*16+kw]=s3;
        }
        __syncwarp();

        float acc[4][8];
#pragma unroll
        for (int u = 0; u < 4; u++)
#pragma unroll
            for (int t = 0; t < 8; t++) acc[u][t] = 0.f;

#pragma unroll 4
        for (int d = 0; d < HD_; d++) {
            const float2* kt2 = (const float2*)(kt + d * KT_STRIDE);
            float2 k0 = kt2[lane];
            float2 k1 = kt2[lane + 32];
            float2 k2 = kt2[lane + 64];
            float q0 = qw[d], q1 = qw[64 + d], q2 = qw[128 + d], q3 = qw[192 + d];
            acc[0][0]=fmaf(q0,k0.x,acc[0][0]); acc[0][1]=fmaf(q0,k0.y,acc[0][1]);
            acc[0][2]=fmaf(q0,k1.x,acc[0][2]); acc[0][3]=fmaf(q0,k1.y,acc[0][3]);
            acc[0][4]=fmaf(q0,k2.x,acc[0][4]); acc[0][5]=fmaf(q0,k2.y,acc[0][5]);
            acc[1][0]=fmaf(q1,k0.x,acc[1][0]); acc[1][1]=fmaf(q1,k0.y,acc[1][1]);
            acc[1][2]=fmaf(q1,k1.x,acc[1][2]); acc[1][3]=fmaf(q1,k1.y,acc[1][3]);
            acc[1][4]=fmaf(q1,k2.x,acc[1][4]); acc[1][5]=fmaf(q1,k2.y,acc[1][5]);
            acc[2][0]=fmaf(q2,k0.x,acc[2][0]); acc[2][1]=fmaf(q2,k0.y,acc[2][1]);
            acc[2][2]=fmaf(q2,k1.x,acc[2][2]); acc[2][3]=fmaf(q2,k1.y,acc[2][3]);
            acc[2][4]=fmaf(q2,k2.x,acc[2][4]); acc[2][5]=fmaf(q2,k2.y,acc[2][5]);
            acc[3][0]=fmaf(q3,k0.x,acc[3][0]); acc[3][1]=fmaf(q3,k0.y,acc[3][1]);
            acc[3][2]=fmaf(q3,k1.x,acc[3][2]); acc[3][3]=fmaf(q3,k1.y,acc[3][3]);
            acc[3][4]=fmaf(q3,k2.x,acc[3][4]); acc[3][5]=fmaf(q3,k2.y,acc[3][5]);
            if (lane < 2) {
                float2 k3 = kt2[lane + 96];
                acc[0][6]=fmaf(q0,k3.x,acc[0][6]); acc[0][7]=fmaf(q0,k3.y,acc[0][7]);
                acc[1][6]=fmaf(q1,k3.x,acc[1][6]); acc[1][7]=fmaf(q1,k3.y,acc[1][7]);
                acc[2][6]=fmaf(q2,k3.x,acc[2][6]); acc[2][7]=fmaf(q2,k3.y,acc[2][7]);
                acc[3][6]=fmaf(q3,k3.x,acc[3][6]); acc[3][7]=fmaf(q3,k3.y,acc[3][7]);
            }
        }

        float inv[4];
        float ex[4][8];
#pragma unroll
        for (int u = 0; u < 4; u++) {
            float sc[8];
#pragma unroll
            for (int c = 0; c < 4; c++) {
                int p = lane + 32 * c;
#pragma unroll
                for (int e = 0; e < 2; e++) {
                    int t = 2 * c + e;
                    sc[t] = (p < 98)
                        ? acc[u][t] * scale + rhw[u*16 + khs[t]] + rww[u*16 + kws[t]]
                        : -INFINITY;
                }
            }
            float mx = -INFINITY;
#pragma unroll
            for (int t = 0; t < 8; t++) mx = fmaxf(mx, sc[t]);
#pragma unroll
            for (int off = 16; off > 0; off >>= 1)
                mx = fmaxf(mx, __shfl_xor_sync(0xffffffffu, mx, off));
            float sum = 0.f;
#pragma unroll
            for (int c = 0; c < 4; c++) {
                int p = lane + 32 * c;
#pragma unroll
                for (int e = 0; e < 2; e++) {
                    int t = 2 * c + e;
                    float pe = (p < 98) ? __expf(sc[t] - mx) : 0.f;
                    ex[u][t] = pe;
                    sum += pe;
                }
            }
#pragma unroll
            for (int off = 16; off > 0; off >>= 1)
                sum += __shfl_xor_sync(0xffffffffu, sum, off);
            inv[u] = 1.f / sum;
        }
#pragma unroll
        for (int c = 0; c < 4; c++) {
            int p = lane + 32 * c;
            if (p < 98) {
                pw4[2*p]   = make_float4(ex[0][2*c],   ex[1][2*c],   ex[2][2*c],   ex[3][2*c]);
                pw4[2*p+1] = make_float4(ex[0][2*c+1], ex[1][2*c+1], ex[2][2*c+1], ex[3][2*c+1]);
            }
        }
        __syncwarp();

        float o00=0.f,o01=0.f,o10=0.f,o11=0.f,o20=0.f,o21=0.f,o30=0.f,o31=0.f;
#pragma unroll 2
        for (int j = 0; j < NTOK; j++) {
            float4 pj = pw4[j];
            float2 vv = vs2[j * 32 + lane];
            o00 = fmaf(pj.x, vv.x, o00); o01 = fmaf(pj.x, vv.y, o01);
            o10 = fmaf(pj.y, vv.x, o10); o11 = fmaf(pj.y, vv.y, o11);
            o20 = fmaf(pj.z, vv.x, o20); o21 = fmaf(pj.z, vv.y, o21);
            o30 = fmaf(pj.w, vv.x, o30); o31 = fmaf(pj.w, vv.y, o31);
        }
        {
            float2* o0 = (float2*)(g_ao + (wdw * NTOK + qbase + 0) * DIM_ + hh * HD_);
            float2* o1 = (float2*)(g_ao + (wdw * NTOK + qbase + 1) * DIM_ + hh * HD_);
            float2* o2 = (float2*)(g_ao + (wdw * NTOK + qbase + 2) * DIM_ + hh * HD_);
            float2* o3 = (float2*)(g_ao + (wdw * NTOK + qbase + 3) * DIM_ + hh * HD_);
            o0[lane] = make_float2(o00 * inv[0], o01 * inv[0]);
            o1[lane] = make_float2(o10 * inv[1], o11 * inv[1]);
            o2[lane] = make_float2(o20 * inv[2], o21 * inv[2]);
            o3[lane] = make_float2(o30 * inv[3], o31 * inv[3]);
        }
        __syncwarp();
    }
}

// =====================================================================
// GEMM 2: out = g_ao @ proj_w^T + proj_b (double-buffered like qkv)
// =====================================================================
__global__ __launch_bounds__(256)
void proj_gemm(const float* __restrict__ w, const float* __restrict__ bias,
               float* __restrict__ out)
{
    __shared__ float As[2][16][132];
    __shared__ float Bs[2][16][132];
    const int tid = threadIdx.x;
    const int m0 = blockIdx.x * 128;
    const int n0 = blockIdx.y * 128;
    const int tx = tid & 15;
    const int ty = tid >> 4;

    int abase[2];
#pragma unroll
    for (int i = 0; i < 2; i++) {
        int lin = tid + 256 * i;
        int row = lin >> 2;
        int gm  = m0 + row;
        abase[i] = (gm < MROWS) ? gm * DIM_ : -1;
    }

    float acc[8][8];
#pragma unroll
    for (int i = 0; i < 8; i++)
#pragma unroll
        for (int j = 0; j < 8; j++) acc[i][j] = 0.f;

    float4 pa[2], pb[2];

#pragma unroll
    for (int i = 0; i < 2; i++) {
        int lin = tid + 256 * i;
        int kq  = (lin & 3) * 4;
        pa[i] = make_float4(0.f, 0.f, 0.f, 0.f);
        if (abase[i] >= 0) pa[i] = *(const float4*)(g_ao + abase[i] + kq);
        int row = lin >> 2;
        pb[i] = *(const float4*)(w + (n0 + row) * DIM_ + kq);
    }
#pragma unroll
    for (int i = 0; i < 2; i++) {
        int lin = tid + 256 * i;
        int row = lin >> 2;
        int kq  = (lin & 3) * 4;
        As[0][kq + 0][row] = pa[i].x; As[0][kq + 1][row] = pa[i].y;
        As[0][kq + 2][row] = pa[i].z; As[0][kq + 3][row] = pa[i].w;
        Bs[0][kq + 0][row] = pb[i].x; Bs[0][kq + 1][row] = pb[i].y;
        Bs[0][kq + 2][row] = pb[i].z; Bs[0][kq + 3][row] = pb[i].w;
    }
    __syncthreads();

    const int NK = DIM_ / 16;   // 48
    for (int c = 0; c < NK; c++) {
        if (c + 1 < NK) {
            int k0 = (c + 1) * 16;
#pragma unroll
            for (int i = 0; i < 2; i++) {
                int lin = tid + 256 * i;
                int kq  = (lin & 3) * 4;
                pa[i] = make_float4(0.f, 0.f, 0.f, 0.f);
                if (abase[i] >= 0) pa[i] = *(const float4*)(g_ao + abase[i] + k0 + kq);
                int row = lin >> 2;
                pb[i] = *(const float4*)(w + (n0 + row) * DIM_ + k0 + kq);
            }
        }

        const int buf = c & 1;
#pragma unroll
        for (int kk = 0; kk < 16; kk++) {
            float a[8], b[8];
            float4 t0 = *(const float4*)&As[buf][kk][ty * 8];
            float4 t1 = *(const float4*)&As[buf][kk][ty * 8 + 4];
            a[0]=t0.x; a[1]=t0.y; a[2]=t0.z; a[3]=t0.w;
            a[4]=t1.x; a[5]=t1.y; a[6]=t1.z; a[7]=t1.w;
            float4 u0 = *(const float4*)&Bs[buf][kk][tx * 8];
            float4 u1 = *(const float4*)&Bs[buf][kk][tx * 8 + 4];
            b[0]=u0.x; b[1]=u0.y; b[2]=u0.z; b[3]=u0.w;
            b[4]=u1.x; b[5]=u1.y; b[6]=u1.z; b[7]=u1.w;
#pragma unroll
            for (int i = 0; i < 8; i++)
#pragma unroll
                for (int j = 0; j < 8; j++)
                    acc[i][j] = fmaf(a[i], b[j], acc[i][j]);
        }

        if (c + 1 < NK) {
            const int nb = (c + 1) & 1;
#pragma unroll
            for (int i = 0; i < 2; i++) {
                int lin = tid + 256 * i;
                int row = lin >> 2;
                int kq  = (lin & 3) * 4;
                As[nb][kq + 0][row] = pa[i].x; As[nb][kq + 1][row] = pa[i].y;
                As[nb][kq + 2][row] = pa[i].z; As[nb][kq + 3][row] = pa[i].w;
                Bs[nb][kq + 0][row] = pb[i].x; Bs[nb][kq + 1][row] = pb[i].y;
                Bs[nb][kq + 2][row] = pb[i].z; Bs[nb][kq + 3][row] = pb[i].w;
            }
        }
        __syncthreads();
    }

#pragma unroll
    for (int i = 0; i < 8; i++) {
        int gm = m0 + ty * 8 + i;
        if (gm >= MROWS) continue;
        int wdw = gm / NTOK, t = gm - wdw * NTOK;
        int b  = wdw / 25,  wi = wdw - b * 25;
        int wh = wi / 5,    ww = wi - wh * 5;
        int th = t / WS_,   tw = t - th * WS_;
        int y  = wh * WS_ + th;
        int xc = ww * WS_ + tw;
        if (y >= IMGHW || xc >= IMGHW) continue;
        float* orow = out + ((b * IMGHW + y) * IMGHW + xc) * DIM_;
#pragma unroll
        for (int j = 0; j < 8; j++) {
            int gn = n0 + tx * 8 + j;
            orow[gn] = acc[i][j] + bias[gn];
        }
    }
}

// =====================================================================
extern "C" void kernel_launch(void* const* d_in, const int* in_sizes, int n_in,
                              void* d_out, int out_size)
{
    const float* x      = (const float*)d_in[0];
    const float* qkv_w  = (const float*)d_in[1];
    const float* qkv_b  = (const float*)d_in[2];
    const float* proj_w = (const float*)d_in[3];
    const float* proj_b = (const float*)d_in[4];
    const float* rph    = (const float*)d_in[5];
    const float* rpw    = (const float*)d_in[6];
    float* out = (float*)d_out;

    cudaFuncSetAttribute(attn_kernel,
                         cudaFuncAttributeMaxDynamicSharedMemorySize,
                         ATTN_SMEM_BYTES);

    dim3 g1((MROWS + 127) / 128, QKV_N / 128);
    qkv_gemm<<<g1, 256>>>(x, qkv_w, qkv_b);

    attn_kernel<<<BH_, 512, ATTN_SMEM_BYTES>>>(rph, rpw);

    dim3 g2((MROWS + 127) / 128, DIM_ / 128);
    proj_gemm<<<g2, 256>>>(proj_w, proj_b, out);
}

// round 12
// speedup vs baseline: 1.2834x; 1.1350x over previous
#include <cuda_runtime.h>
#include <math.h>

#define WS_      14
#define NTOK     196
#define NH_      12
#define HD_      64
#define DIM_     768
#define NWIN     200
#define BH_      2400
#define MROWS    39200
#define IMGHW    64
#define QKV_N    2304
#define NN_      38416   // 196*196
#define RELSZ    2744    // 196*14

// ---- scratch ----
__device__ float g_q   [BH_ * NTOK * HD_];
__device__ float g_k   [BH_ * NTOK * HD_];
__device__ float g_v   [BH_ * NTOK * HD_];
__device__ float g_ao  [MROWS * DIM_];
__device__ float g_s   [BH_ * NN_];      // scores / probs (369 MB)
__device__ float g_relh[BH_ * RELSZ];
__device__ float g_relw[BH_ * RELSZ];

// =====================================================================
// GEMM 1: qkv = gather(x) @ qkv_w^T + qkv_b  (round-10 version, passing)
// =====================================================================
__global__ __launch_bounds__(256)
void qkv_gemm(const float* __restrict__ x, const float* __restrict__ w,
              const float* __restrict__ bias)
{
    __shared__ float As[2][16][132];
    __shared__ float Bs[2][16][132];
    const int tid = threadIdx.x;
    const int m0 = blockIdx.x * 128;
    const int n0 = blockIdx.y * 128;
    const int tx = tid & 15;
    const int ty = tid >> 4;

    int abase[2];
#pragma unroll
    for (int i = 0; i < 2; i++) {
        int lin = tid + 256 * i;
        int row = lin >> 2;
        int gm  = m0 + row;
        int base = -1;
        if (gm < MROWS) {
            int wdw = gm / NTOK, t = gm - wdw * NTOK;
            int b  = wdw / 25,  wi = wdw - b * 25;
            int wh = wi / 5,    ww = wi - wh * 5;
            int th = t / WS_,   tw = t - th * WS_;
            int y  = wh * WS_ + th;
            int xc = ww * WS_ + tw;
            if (y < IMGHW && xc < IMGHW)
                base = ((b * IMGHW + y) * IMGHW + xc) * DIM_;
        }
        abase[i] = base;
    }

    float acc[8][8];
#pragma unroll
    for (int i = 0; i < 8; i++)
#pragma unroll
        for (int j = 0; j < 8; j++) acc[i][j] = 0.f;

    float4 pa[2], pb[2];
#pragma unroll
    for (int i = 0; i < 2; i++) {
        int lin = tid + 256 * i;
        int kq  = (lin & 3) * 4;
        pa[i] = make_float4(0.f, 0.f, 0.f, 0.f);
        if (abase[i] >= 0) pa[i] = *(const float4*)(x + abase[i] + kq);
        int row = lin >> 2;
        pb[i] = *(const float4*)(w + (n0 + row) * DIM_ + kq);
    }
#pragma unroll
    for (int i = 0; i < 2; i++) {
        int lin = tid + 256 * i;
        int row = lin >> 2;
        int kq  = (lin & 3) * 4;
        As[0][kq + 0][row] = pa[i].x; As[0][kq + 1][row] = pa[i].y;
        As[0][kq + 2][row] = pa[i].z; As[0][kq + 3][row] = pa[i].w;
        Bs[0][kq + 0][row] = pb[i].x; Bs[0][kq + 1][row] = pb[i].y;
        Bs[0][kq + 2][row] = pb[i].z; Bs[0][kq + 3][row] = pb[i].w;
    }
    __syncthreads();

    const int NK = DIM_ / 16;
    for (int c = 0; c < NK; c++) {
        if (c + 1 < NK) {
            int k0 = (c + 1) * 16;
#pragma unroll
            for (int i = 0; i < 2; i++) {
                int lin = tid + 256 * i;
                int kq  = (lin & 3) * 4;
                pa[i] = make_float4(0.f, 0.f, 0.f, 0.f);
                if (abase[i] >= 0) pa[i] = *(const float4*)(x + abase[i] + k0 + kq);
                int row = lin >> 2;
                pb[i] = *(const float4*)(w + (n0 + row) * DIM_ + k0 + kq);
            }
        }
        const int buf = c & 1;
#pragma unroll
        for (int kk = 0; kk < 16; kk++) {
            float a[8], b[8];
            float4 t0 = *(const float4*)&As[buf][kk][ty * 8];
            float4 t1 = *(const float4*)&As[buf][kk][ty * 8 + 4];
            a[0]=t0.x; a[1]=t0.y; a[2]=t0.z; a[3]=t0.w;
            a[4]=t1.x; a[5]=t1.y; a[6]=t1.z; a[7]=t1.w;
            float4 u0 = *(const float4*)&Bs[buf][kk][tx * 8];
            float4 u1 = *(const float4*)&Bs[buf][kk][tx * 8 + 4];
            b[0]=u0.x; b[1]=u0.y; b[2]=u0.z; b[3]=u0.w;
            b[4]=u1.x; b[5]=u1.y; b[6]=u1.z; b[7]=u1.w;
#pragma unroll
            for (int i = 0; i < 8; i++)
#pragma unroll
                for (int j = 0; j < 8; j++)
                    acc[i][j] = fmaf(a[i], b[j], acc[i][j]);
        }
        if (c + 1 < NK) {
            const int nb = (c + 1) & 1;
#pragma unroll
            for (int i = 0; i < 2; i++) {
                int lin = tid + 256 * i;
                int row = lin >> 2;
                int kq  = (lin & 3) * 4;
                As[nb][kq + 0][row] = pa[i].x; As[nb][kq + 1][row] = pa[i].y;
                As[nb][kq + 2][row] = pa[i].z; As[nb][kq + 3][row] = pa[i].w;
                Bs[nb][kq + 0][row] = pb[i].x; Bs[nb][kq + 1][row] = pb[i].y;
                Bs[nb][kq + 2][row] = pb[i].z; Bs[nb][kq + 3][row] = pb[i].w;
            }
        }
        __syncthreads();
    }

#pragma unroll
    for (int i = 0; i < 8; i++) {
        int gm = m0 + ty * 8 + i;
        if (gm >= MROWS) continue;
        int wdw = gm / NTOK, t = gm - wdw * NTOK;
#pragma unroll
        for (int j = 0; j < 8; j++) {
            int gn = n0 + tx * 8 + j;
            float c = acc[i][j] + bias[gn];
            int which = gn / DIM_;
            int r = gn - which * DIM_;
            int h = r >> 6, d = r & 63;
            int idx = ((wdw * NH_ + h) * NTOK + t) * HD_ + d;
            float* dst = (which == 0) ? g_q : ((which == 1) ? g_k : g_v);
            dst[idx] = c;
        }
    }
}

// =====================================================================
// rel kernel: rel_h[bh,qi,kh] = q[qi]·rph[qh-kh+13],  same for rel_w
// =====================================================================
__global__ __launch_bounds__(256)
void rel_kernel(const float* __restrict__ rph, const float* __restrict__ rpw)
{
    const int bh = blockIdx.x;
    const float* q = g_q + bh * (NTOK * HD_);
    for (int id = threadIdx.x; id < 2 * RELSZ; id += 256) {
        int isW = (id >= RELSZ);
        int lid = isW ? id - RELSZ : id;
        int qi = lid / WS_, kk = lid - qi * WS_;
        int qh = qi / WS_, qwc = qi - qh * WS_;
        const float* table = isW ? rpw : rph;
        int ridx = (isW ? qwc : qh) - kk + (WS_ - 1);
        const float* r  = table + ridx * HD_;
        const float* qp = q + qi * HD_;
        float s = 0.f;
#pragma unroll
        for (int d = 0; d < HD_; d++)
            s = fmaf(__ldg(qp + d), __ldg(r + d), s);
        float* dst = isW ? g_relw : g_relh;
        dst[bh * RELSZ + lid] = s;
    }
}

// =====================================================================
// scores GEMM: S = 0.125*Q@K^T + relh + relw   per bh (196x196x64)
// grid (2,2,2400), block 256, tile 128x128, BK=16 double-buffered
// =====================================================================
__global__ __launch_bounds__(256)
void scores_gemm()
{
    __shared__ float As[2][16][132];
    __shared__ float Bs[2][16][132];
    const int tid = threadIdx.x;
    const int bh = blockIdx.z;
    const int m0 = blockIdx.x * 128;
    const int n0 = blockIdx.y * 128;
    const int tx = tid & 15;
    const int ty = tid >> 4;
    const float* Q = g_q + bh * (NTOK * HD_);
    const float* K = g_k + bh * (NTOK * HD_);

    float acc[8][8];
#pragma unroll
    for (int i = 0; i < 8; i++)
#pragma unroll
        for (int j = 0; j < 8; j++) acc[i][j] = 0.f;

    float4 pa[2], pb[2];
#pragma unroll
    for (int i = 0; i < 2; i++) {
        int lin = tid + 256 * i;
        int row = lin >> 2;
        int kq  = (lin & 3) * 4;
        pa[i] = make_float4(0.f, 0.f, 0.f, 0.f);
        pb[i] = make_float4(0.f, 0.f, 0.f, 0.f);
        if (m0 + row < NTOK) pa[i] = *(const float4*)(Q + (m0 + row) * HD_ + kq);
        if (n0 + row < NTOK) pb[i] = *(const float4*)(K + (n0 + row) * HD_ + kq);
    }
#pragma unroll
    for (int i = 0; i < 2; i++) {
        int lin = tid + 256 * i;
        int row = lin >> 2;
        int kq  = (lin & 3) * 4;
        As[0][kq + 0][row] = pa[i].x; As[0][kq + 1][row] = pa[i].y;
        As[0][kq + 2][row] = pa[i].z; As[0][kq + 3][row] = pa[i].w;
        Bs[0][kq + 0][row] = pb[i].x; Bs[0][kq + 1][row] = pb[i].y;
        Bs[0][kq + 2][row] = pb[i].z; Bs[0][kq + 3][row] = pb[i].w;
    }
    __syncthreads();

    const int NK = HD_ / 16;    // 4
    for (int c = 0; c < NK; c++) {
        if (c + 1 < NK) {
            int k0 = (c + 1) * 16;
#pragma unroll
            for (int i = 0; i < 2; i++) {
                int lin = tid + 256 * i;
                int row = lin >> 2;
                int kq  = (lin & 3) * 4;
                pa[i] = make_float4(0.f, 0.f, 0.f, 0.f);
                pb[i] = make_float4(0.f, 0.f, 0.f, 0.f);
                if (m0 + row < NTOK) pa[i] = *(const float4*)(Q + (m0 + row) * HD_ + k0 + kq);
                if (n0 + row < NTOK) pb[i] = *(const float4*)(K + (n0 + row) * HD_ + k0 + kq);
            }
        }
        const int buf = c & 1;
#pragma unroll
        for (int kk = 0; kk < 16; kk++) {
            float a[8], b[8];
            float4 t0 = *(const float4*)&As[buf][kk][ty * 8];
            float4 t1 = *(const float4*)&As[buf][kk][ty * 8 + 4];
            a[0]=t0.x; a[1]=t0.y; a[2]=t0.z; a[3]=t0.w;
            a[4]=t1.x; a[5]=t1.y; a[6]=t1.z; a[7]=t1.w;
            float4 u0 = *(const float4*)&Bs[buf][kk][tx * 8];
            float4 u1 = *(const float4*)&Bs[buf][kk][tx * 8 + 4];
            b[0]=u0.x; b[1]=u0.y; b[2]=u0.z; b[3]=u0.w;
            b[4]=u1.x; b[5]=u1.y; b[6]=u1.z; b[7]=u1.w;
#pragma unroll
            for (int i = 0; i < 8; i++)
#pragma unroll
                for (int j = 0; j < 8; j++)
                    acc[i][j] = fmaf(a[i], b[j], acc[i][j]);
        }
        if (c + 1 < NK) {
            const int nb = (c + 1) & 1;
#pragma unroll
            for (int i = 0; i < 2; i++) {
                int lin = tid + 256 * i;
                int row = lin >> 2;
                int kq  = (lin & 3) * 4;
                As[nb][kq + 0][row] = pa[i].x; As[nb][kq + 1][row] = pa[i].y;
                As[nb][kq + 2][row] = pa[i].z; As[nb][kq + 3][row] = pa[i].w;
                Bs[nb][kq + 0][row] = pb[i].x; Bs[nb][kq + 1][row] = pb[i].y;
                Bs[nb][kq + 2][row] = pb[i].z; Bs[nb][kq + 3][row] = pb[i].w;
            }
        }
        __syncthreads();
    }

    // epilogue: scale + rel-pos bias, store to g_s
    const float* rhb = g_relh + bh * RELSZ;
    const float* rwb = g_relw + bh * RELSZ;
    int khs[8], kws[8];
#pragma unroll
    for (int j = 0; j < 8; j++) {
        int gn = n0 + tx * 8 + j;
        int kh = gn / WS_;
        khs[j] = kh;
        kws[j] = gn - kh * WS_;
    }
#pragma unroll
    for (int i = 0; i < 8; i++) {
        int gm = m0 + ty * 8 + i;
        if (gm >= NTOK) continue;
        float* srow = g_s + (size_t)bh * NN_ + gm * NTOK;
        const float* rh = rhb + gm * WS_;
        const float* rw = rwb + gm * WS_;
#pragma unroll
        for (int j = 0; j < 8; j++) {
            int gn = n0 + tx * 8 + j;
            if (gn >= NTOK) continue;
            srow[gn] = acc[i][j] * 0.125f + __ldg(rh + khs[j]) + __ldg(rw + kws[j]);
        }
    }
}

// =====================================================================
// softmax: one warp per row of 196
// =====================================================================
__global__ __launch_bounds__(128)
void softmax_kernel()
{
    const int lane = threadIdx.x & 31;
    const size_t row = (size_t)blockIdx.x * 4 + (threadIdx.x >> 5);
    float* s = g_s + row * NTOK;

    float v[7];
    float mx = -INFINITY;
#pragma unroll
    for (int t = 0; t < 7; t++) {
        int j = lane + 32 * t;
        v[t] = (j < NTOK) ? s[j] : -INFINITY;
        mx = fmaxf(mx, v[t]);
    }
#pragma unroll
    for (int off = 16; off > 0; off >>= 1)
        mx = fmaxf(mx, __shfl_xor_sync(0xffffffffu, mx, off));
    float sum = 0.f;
#pragma unroll
    for (int t = 0; t < 7; t++) {
        int j = lane + 32 * t;
        if (j < NTOK) {
            float e = __expf(v[t] - mx);
            v[t] = e;
            sum += e;
        }
    }
#pragma unroll
    for (int off = 16; off > 0; off >>= 1)
        sum += __shfl_xor_sync(0xffffffffu, sum, off);
    float inv = 1.f / sum;
#pragma unroll
    for (int t = 0; t < 7; t++) {
        int j = lane + 32 * t;
        if (j < NTOK) s[j] = v[t] * inv;
    }
}

// =====================================================================
// AV GEMM: O = P@V per bh.  M=196 (2 tiles of 128), N=64, K=196.
// block 256 = 32(ty) x 8(tx), microtile 4x8.  BK=16 double-buffered,
// V staged transposed.  Output scattered into g_ao.
// =====================================================================
__global__ __launch_bounds__(256)
void av_gemm()
{
    __shared__ float As[2][16][132];
    __shared__ float Bs[2][16][68];
    const int tid = threadIdx.x;
    const int bh = blockIdx.z;
    const int m0 = blockIdx.x * 128;
    const int tx = tid & 7;
    const int ty = tid >> 3;
    const float* P = g_s + (size_t)bh * NN_;
    const float* V = g_v + bh * (NTOK * HD_);
    const int wdw = bh / NH_, hh = bh - wdw * NH_;

    float acc[4][8];
#pragma unroll
    for (int i = 0; i < 4; i++)
#pragma unroll
        for (int j = 0; j < 8; j++) acc[i][j] = 0.f;

    const int NC = 13;   // 12 full chunks of 16 + tail of 4 (zero-padded)
    float4 pa[2], pb;

    // prologue: stage 0
#pragma unroll
    for (int i = 0; i < 2; i++) {
        int lin = tid + 256 * i;
        int row = lin >> 2;
        int kq  = (lin & 3) * 4;
        pa[i] = make_float4(0.f, 0.f, 0.f, 0.f);
        if (m0 + row < NTOK && kq < NTOK)
            pa[i] = *(const float4*)(P + (m0 + row) * NTOK + kq);
    }
    {
        int vrow = tid >> 4;            // 0..15
        int c4   = (tid & 15) * 4;      // 0..60
        pb = make_float4(0.f, 0.f, 0.f, 0.f);
        if (vrow < NTOK) pb = *(const float4*)(V + vrow * HD_ + c4);
    }
#pragma unroll
    for (int i = 0; i < 2; i++) {
        int lin = tid + 256 * i;
        int row = lin >> 2;
        int kq  = (lin & 3) * 4;
        As[0][kq + 0][row] = pa[i].x; As[0][kq + 1][row] = pa[i].y;
        As[0][kq + 2][row] = pa[i].z; As[0][kq + 3][row] = pa[i].w;
    }
    {
        int vrow = tid >> 4;
        int c4   = (tid & 15) * 4;
        *(float4*)&Bs[0][vrow][c4] = pb;
    }
    __syncthreads();

    for (int c = 0; c < NC; c++) {
        if (c + 1 < NC) {
            int k0 = (c + 1) * 16;
#pragma unroll
            for (int i = 0; i < 2; i++) {
                int lin = tid + 256 * i;
                int row = lin >> 2;
                int kq  = (lin & 3) * 4;
                pa[i] = make_float4(0.f, 0.f, 0.f, 0.f);
                if (m0 + row < NTOK && k0 + kq < NTOK)
                    pa[i] = *(const float4*)(P + (m0 + row) * NTOK + k0 + kq);
            }
            int vrow = tid >> 4;
            int c4   = (tid & 15) * 4;
            pb = make_float4(0.f, 0.f, 0.f, 0.f);
            if (k0 + vrow < NTOK) pb = *(const float4*)(V + (k0 + vrow) * HD_ + c4);
        }
        const int buf = c & 1;
#pragma unroll
        for (int kk = 0; kk < 16; kk++) {
            float a[4], b[8];
            float4 t0 = *(const float4*)&As[buf][kk][ty * 4];
            a[0]=t0.x; a[1]=t0.y; a[2]=t0.z; a[3]=t0.w;
            float4 u0 = *(const float4*)&Bs[buf][kk][tx * 8];
            float4 u1 = *(const float4*)&Bs[buf][kk][tx * 8 + 4];
            b[0]=u0.x; b[1]=u0.y; b[2]=u0.z; b[3]=u0.w;
            b[4]=u1.x; b[5]=u1.y; b[6]=u1.z; b[7]=u1.w;
#pragma unroll
            for (int i = 0; i < 4; i++)
#pragma unroll
                for (int j = 0; j < 8; j++)
                    acc[i][j] = fmaf(a[i], b[j], acc[i][j]);
        }
        if (c + 1 < NC) {
            const int nb = (c + 1) & 1;
#pragma unroll
            for (int i = 0; i < 2; i++) {
                int lin = tid + 256 * i;
                int row = lin >> 2;
                int kq  = (lin & 3) * 4;
                As[nb][kq + 0][row] = pa[i].x; As[nb][kq + 1][row] = pa[i].y;
                As[nb][kq + 2][row] = pa[i].z; As[nb][kq + 3][row] = pa[i].w;
            }
            int vrow = tid >> 4;
            int c4   = (tid & 15) * 4;
            *(float4*)&Bs[nb][vrow][c4] = pb;
        }
        __syncthreads();
    }

    // epilogue: O[gm][hh*64 + n]
#pragma unroll
    for (int i = 0; i < 4; i++) {
        int gm = m0 + ty * 4 + i;
        if (gm >= NTOK) continue;
        float* orow = g_ao + (size_t)(wdw * NTOK + gm) * DIM_ + hh * HD_ + tx * 8;
        orow[0] = acc[i][0]; orow[1] = acc[i][1];
        orow[2] = acc[i][2]; orow[3] = acc[i][3];
        orow[4] = acc[i][4]; orow[5] = acc[i][5];
        orow[6] = acc[i][6]; orow[7] = acc[i][7];
    }
}

// =====================================================================
// GEMM 2: out = g_ao @ proj_w^T + proj_b  (round-10 version, passing)
// =====================================================================
__global__ __launch_bounds__(256)
void proj_gemm(const float* __restrict__ w, const float* __restrict__ bias,
               float* __restrict__ out)
{
    __shared__ float As[2][16][132];
    __shared__ float Bs[2][16][132];
    const int tid = threadIdx.x;
    const int m0 = blockIdx.x * 128;
    const int n0 = blockIdx.y * 128;
    const int tx = tid & 15;
    const int ty = tid >> 4;

    int abase[2];
#pragma unroll
    for (int i = 0; i < 2; i++) {
        int lin = tid + 256 * i;
        int row = lin >> 2;
        int gm  = m0 + row;
        abase[i] = (gm < MROWS) ? gm * DIM_ : -1;
    }

    float acc[8][8];
#pragma unroll
    for (int i = 0; i < 8; i++)
#pragma unroll
        for (int j = 0; j < 8; j++) acc[i][j] = 0.f;

    float4 pa[2], pb[2];
#pragma unroll
    for (int i = 0; i < 2; i++) {
        int lin = tid + 256 * i;
        int kq  = (lin & 3) * 4;
        pa[i] = make_float4(0.f, 0.f, 0.f, 0.f);
        if (abase[i] >= 0) pa[i] = *(const float4*)(g_ao + abase[i] + kq);
        int row = lin >> 2;
        pb[i] = *(const float4*)(w + (n0 + row) * DIM_ + kq);
    }
#pragma unroll
    for (int i = 0; i < 2; i++) {
        int lin = tid + 256 * i;
        int row = lin >> 2;
        int kq  = (lin & 3) * 4;
        As[0][kq + 0][row] = pa[i].x; As[0][kq + 1][row] = pa[i].y;
        As[0][kq + 2][row] = pa[i].z; As[0][kq + 3][row] = pa[i].w;
        Bs[0][kq + 0][row] = pb[i].x; Bs[0][kq + 1][row] = pb[i].y;
        Bs[0][kq + 2][row] = pb[i].z; Bs[0][kq + 3][row] = pb[i].w;
    }
    __syncthreads();

    const int NK = DIM_ / 16;
    for (int c = 0; c < NK; c++) {
        if (c + 1 < NK) {
            int k0 = (c + 1) * 16;
#pragma unroll
            for (int i = 0; i < 2; i++) {
                int lin = tid + 256 * i;
                int kq  = (lin & 3) * 4;
                pa[i] = make_float4(0.f, 0.f, 0.f, 0.f);
                if (abase[i] >= 0) pa[i] = *(const float4*)(g_ao + abase[i] + k0 + kq);
                int row = lin >> 2;
                pb[i] = *(const float4*)(w + (n0 + row) * DIM_ + k0 + kq);
            }
        }
        const int buf = c & 1;
#pragma unroll
        for (int kk = 0; kk < 16; kk++) {
            float a[8], b[8];
            float4 t0 = *(const float4*)&As[buf][kk][ty * 8];
            float4 t1 = *(const float4*)&As[buf][kk][ty * 8 + 4];
            a[0]=t0.x; a[1]=t0.y; a[2]=t0.z; a[3]=t0.w;
            a[4]=t1.x; a[5]=t1.y; a[6]=t1.z; a[7]=t1.w;
            float4 u0 = *(const float4*)&Bs[buf][kk][tx * 8];
            float4 u1 = *(const float4*)&Bs[buf][kk][tx * 8 + 4];
            b[0]=u0.x; b[1]=u0.y; b[2]=u0.z; b[3]=u0.w;
            b[4]=u1.x; b[5]=u1.y; b[6]=u1.z; b[7]=u1.w;
#pragma unroll
            for (int i = 0; i < 8; i++)
#pragma unroll
                for (int j = 0; j < 8; j++)
                    acc[i][j] = fmaf(a[i], b[j], acc[i][j]);
        }
        if (c + 1 < NK) {
            const int nb = (c + 1) & 1;
#pragma unroll
            for (int i = 0; i < 2; i++) {
                int lin = tid + 256 * i;
                int row = lin >> 2;
                int kq  = (lin & 3) * 4;
                As[nb][kq + 0][row] = pa[i].x; As[nb][kq + 1][row] = pa[i].y;
                As[nb][kq + 2][row] = pa[i].z; As[nb][kq + 3][row] = pa[i].w;
                Bs[nb][kq + 0][row] = pb[i].x; Bs[nb][kq + 1][row] = pb[i].y;
                Bs[nb][kq + 2][row] = pb[i].z; Bs[nb][kq + 3][row] = pb[i].w;
            }
        }
        __syncthreads();
    }

#pragma unroll
    for (int i = 0; i < 8; i++) {
        int gm = m0 + ty * 8 + i;
        if (gm >= MROWS) continue;
        int wdw = gm / NTOK, t = gm - wdw * NTOK;
        int b  = wdw / 25,  wi = wdw - b * 25;
        int wh = wi / 5,    ww = wi - wh * 5;
        int th = t / WS_,   tw = t - th * WS_;
        int y  = wh * WS_ + th;
        int xc = ww * WS_ + tw;
        if (y >= IMGHW || xc >= IMGHW) continue;
        float* orow = out + ((b * IMGHW + y) * IMGHW + xc) * DIM_;
#pragma unroll
        for (int j = 0; j < 8; j++) {
            int gn = n0 + tx * 8 + j;
            orow[gn] = acc[i][j] + bias[gn];
        }
    }
}

// =====================================================================
extern "C" void kernel_launch(void* const* d_in, const int* in_sizes, int n_in,
                              void* d_out, int out_size)
{
    const float* x      = (const float*)d_in[0];
    const float* qkv_w  = (const float*)d_in[1];
    const float* qkv_b  = (const float*)d_in[2];
    const float* proj_w = (const float*)d_in[3];
    const float* proj_b = (const float*)d_in[4];
    const float* rph    = (const float*)d_in[5];
    const float* rpw    = (const float*)d_in[6];
    float* out = (float*)d_out;

    dim3 g1((MROWS + 127) / 128, QKV_N / 128);
    qkv_gemm<<<g1, 256>>>(x, qkv_w, qkv_b);

    rel_kernel<<<BH_, 256>>>(rph, rpw);

    dim3 gs(2, 2, BH_);
    scores_gemm<<<gs, 256>>>();

    softmax_kernel<<<(BH_ * NTOK) / 4, 128>>>();

    dim3 ga(2, 1, BH_);
    av_gemm<<<ga, 256>>>();

    dim3 g2((MROWS + 127) / 128, DIM_ / 128);
    proj_gemm<<<g2, 256>>>(proj_w, proj_b, out);
}

// round 13
// speedup vs baseline: 1.3304x; 1.0366x over previous
#include <cuda_runtime.h>
#include <math.h>

#define WS_      14
#define NTOK     196
#define NH_      12
#define HD_      64
#define DIM_     768
#define NWIN     200
#define BH_      2400
#define MROWS    39200
#define IMGHW    64
#define QKV_N    2304
#define NN_      38416   // 196*196

// ---- scratch ----
__device__ float g_q   [BH_ * NTOK * HD_];
__device__ float g_k   [BH_ * NTOK * HD_];
__device__ float g_v   [BH_ * NTOK * HD_];
__device__ float g_ao  [MROWS * DIM_];
__device__ float g_s   [BH_ * NN_];      // scores / probs (369 MB)

// =====================================================================
// GEMM 1: qkv = gather(x) @ qkv_w^T + qkv_b  (passing round-10/12 version)
// =====================================================================
__global__ __launch_bounds__(256)
void qkv_gemm(const float* __restrict__ x, const float* __restrict__ w,
              const float* __restrict__ bias)
{
    __shared__ float As[2][16][132];
    __shared__ float Bs[2][16][132];
    const int tid = threadIdx.x;
    const int m0 = blockIdx.x * 128;
    const int n0 = blockIdx.y * 128;
    const int tx = tid & 15;
    const int ty = tid >> 4;

    int abase[2];
#pragma unroll
    for (int i = 0; i < 2; i++) {
        int lin = tid + 256 * i;
        int row = lin >> 2;
        int gm  = m0 + row;
        int base = -1;
        if (gm < MROWS) {
            int wdw = gm / NTOK, t = gm - wdw * NTOK;
            int b  = wdw / 25,  wi = wdw - b * 25;
            int wh = wi / 5,    ww = wi - wh * 5;
            int th = t / WS_,   tw = t - th * WS_;
            int y  = wh * WS_ + th;
            int xc = ww * WS_ + tw;
            if (y < IMGHW && xc < IMGHW)
                base = ((b * IMGHW + y) * IMGHW + xc) * DIM_;
        }
        abase[i] = base;
    }

    float acc[8][8];
#pragma unroll
    for (int i = 0; i < 8; i++)
#pragma unroll
        for (int j = 0; j < 8; j++) acc[i][j] = 0.f;

    float4 pa[2], pb[2];
#pragma unroll
    for (int i = 0; i < 2; i++) {
        int lin = tid + 256 * i;
        int kq  = (lin & 3) * 4;
        pa[i] = make_float4(0.f, 0.f, 0.f, 0.f);
        if (abase[i] >= 0) pa[i] = *(const float4*)(x + abase[i] + kq);
        int row = lin >> 2;
        pb[i] = *(const float4*)(w + (n0 + row) * DIM_ + kq);
    }
#pragma unroll
    for (int i = 0; i < 2; i++) {
        int lin = tid + 256 * i;
        int row = lin >> 2;
        int kq  = (lin & 3) * 4;
        As[0][kq + 0][row] = pa[i].x; As[0][kq + 1][row] = pa[i].y;
        As[0][kq + 2][row] = pa[i].z; As[0][kq + 3][row] = pa[i].w;
        Bs[0][kq + 0][row] = pb[i].x; Bs[0][kq + 1][row] = pb[i].y;
        Bs[0][kq + 2][row] = pb[i].z; Bs[0][kq + 3][row] = pb[i].w;
    }
    __syncthreads();

    const int NK = DIM_ / 16;
    for (int c = 0; c < NK; c++) {
        if (c + 1 < NK) {
            int k0 = (c + 1) * 16;
#pragma unroll
            for (int i = 0; i < 2; i++) {
                int lin = tid + 256 * i;
                int kq  = (lin & 3) * 4;
                pa[i] = make_float4(0.f, 0.f, 0.f, 0.f);
                if (abase[i] >= 0) pa[i] = *(const float4*)(x + abase[i] + k0 + kq);
                int row = lin >> 2;
                pb[i] = *(const float4*)(w + (n0 + row) * DIM_ + k0 + kq);
            }
        }
        const int buf = c & 1;
#pragma unroll
        for (int kk = 0; kk < 16; kk++) {
            float a[8], b[8];
            float4 t0 = *(const float4*)&As[buf][kk][ty * 8];
            float4 t1 = *(const float4*)&As[buf][kk][ty * 8 + 4];
            a[0]=t0.x; a[1]=t0.y; a[2]=t0.z; a[3]=t0.w;
            a[4]=t1.x; a[5]=t1.y; a[6]=t1.z; a[7]=t1.w;
            float4 u0 = *(const float4*)&Bs[buf][kk][tx * 8];
            float4 u1 = *(const float4*)&Bs[buf][kk][tx * 8 + 4];
            b[0]=u0.x; b[1]=u0.y; b[2]=u0.z; b[3]=u0.w;
            b[4]=u1.x; b[5]=u1.y; b[6]=u1.z; b[7]=u1.w;
#pragma unroll
            for (int i = 0; i < 8; i++)
#pragma unroll
                for (int j = 0; j < 8; j++)
                    acc[i][j] = fmaf(a[i], b[j], acc[i][j]);
        }
        if (c + 1 < NK) {
            const int nb = (c + 1) & 1;
#pragma unroll
            for (int i = 0; i < 2; i++) {
                int lin = tid + 256 * i;
                int row = lin >> 2;
                int kq  = (lin & 3) * 4;
                As[nb][kq + 0][row] = pa[i].x; As[nb][kq + 1][row] = pa[i].y;
                As[nb][kq + 2][row] = pa[i].z; As[nb][kq + 3][row] = pa[i].w;
                Bs[nb][kq + 0][row] = pb[i].x; Bs[nb][kq + 1][row] = pb[i].y;
                Bs[nb][kq + 2][row] = pb[i].z; Bs[nb][kq + 3][row] = pb[i].w;
            }
        }
        __syncthreads();
    }

#pragma unroll
    for (int i = 0; i < 8; i++) {
        int gm = m0 + ty * 8 + i;
        if (gm >= MROWS) continue;
        int wdw = gm / NTOK, t = gm - wdw * NTOK;
#pragma unroll
        for (int j = 0; j < 8; j++) {
            int gn = n0 + tx * 8 + j;
            float c = acc[i][j] + bias[gn];
            int which = gn / DIM_;
            int r = gn - which * DIM_;
            int h = r >> 6, d = r & 63;
            int idx = ((wdw * NH_ + h) * NTOK + t) * HD_ + d;
            float* dst = (which == 0) ? g_q : ((which == 1) ? g_k : g_v);
            dst[idx] = c;
        }
    }
}

// =====================================================================
// scores v2: fully-staged, rel-fused.
// grid (2, BH_), block 256.  Per CTA: M-tile 128 queries of one bh.
//   As[64][132]: Q tile transposed (staged once)
//   Bs[64][132]: K half-tile transposed (staged per N-half)
//   relh/relw[128][16]: per-row rel-pos partial dots (computed in-CTA)
// GEMM: 2 halves x 64 straight FMA iters, 8x8 microtile.
// =====================================================================
#define SC_SMEM_FLOATS (8448 + 8448 + 2048 + 2048)
#define SC_SMEM_BYTES  (SC_SMEM_FLOATS * 4)

__global__ __launch_bounds__(256)
void scores_gemm(const float* __restrict__ rph, const float* __restrict__ rpw)
{
    extern __shared__ float sm[];
    float* As   = sm;              // [64][132] d-major
    float* Bs   = As + 8448;       // [64][132]
    float* relh = Bs + 8448;       // [128][16]
    float* relw = relh + 2048;     // [128][16]

    const int tid = threadIdx.x;
    const int bh  = blockIdx.y;
    const int m0  = blockIdx.x * 128;
    const int tx  = tid & 15;
    const int ty  = tid >> 4;
    const float* Q = g_q + bh * (NTOK * HD_);
    const float* K = g_k + bh * (NTOK * HD_);

    // ---- stage Q tile transposed: As[d][row] ----
#pragma unroll
    for (int i = 0; i < 8; i++) {
        int e = tid + 256 * i;        // 0..2047
        int row = e >> 4;             // 0..127
        int d0  = (e & 15) * 4;
        float4 v = make_float4(0.f, 0.f, 0.f, 0.f);
        if (m0 + row < NTOK) v = *(const float4*)(Q + (m0 + row) * HD_ + d0);
        As[(d0 + 0) * 132 + row] = v.x;
        As[(d0 + 1) * 132 + row] = v.y;
        As[(d0 + 2) * 132 + row] = v.z;
        As[(d0 + 3) * 132 + row] = v.w;
    }
    __syncthreads();

    // ---- rel-pos partial dots from staged Q ----
    // tasks: 2 * 128 * 14 = 3584; 14 per thread
#pragma unroll
    for (int i = 0; i < 14; i++) {
        int T = tid + 256 * i;
        if (T >= 3584) break;
        int isW = (T >= 1792);
        int lid = isW ? T - 1792 : T;
        int row = lid / WS_;
        int kk  = lid - row * WS_;
        int gm  = m0 + row;
        float s = 0.f;
        if (gm < NTOK) {
            int qh  = gm / WS_;
            int qwc = gm - qh * WS_;
            int ridx = (isW ? qwc : qh) - kk + (WS_ - 1);
            const float* r = (isW ? rpw : rph) + ridx * HD_;
#pragma unroll
            for (int d = 0; d < HD_; d++)
                s = fmaf(As[d * 132 + row], __ldg(r + d), s);
        }
        (isW ? relw : relh)[row * 16 + kk] = s;
    }

    for (int half = 0; half < 2; half++) {
        const int n0 = half * 128;
        // ---- stage K half-tile transposed: Bs[d][krow] ----
        // (rel compute above and B staging both follow the A sync)
#pragma unroll
        for (int i = 0; i < 8; i++) {
            int e = tid + 256 * i;
            int row = e >> 4;
            int d0  = (e & 15) * 4;
            float4 v = make_float4(0.f, 0.f, 0.f, 0.f);
            if (n0 + row < NTOK) v = *(const float4*)(K + (n0 + row) * HD_ + d0);
            Bs[(d0 + 0) * 132 + row] = v.x;
            Bs[(d0 + 1) * 132 + row] = v.y;
            Bs[(d0 + 2) * 132 + row] = v.z;
            Bs[(d0 + 3) * 132 + row] = v.w;
        }
        __syncthreads();

        float acc[8][8];
#pragma unroll
        for (int i = 0; i < 8; i++)
#pragma unroll
            for (int j = 0; j < 8; j++) acc[i][j] = 0.f;

#pragma unroll 8
        for (int kk = 0; kk < HD_; kk++) {
            float a[8], b[8];
            float4 t0 = *(const float4*)&As[kk * 132 + ty * 8];
            float4 t1 = *(const float4*)&As[kk * 132 + ty * 8 + 4];
            a[0]=t0.x; a[1]=t0.y; a[2]=t0.z; a[3]=t0.w;
            a[4]=t1.x; a[5]=t1.y; a[6]=t1.z; a[7]=t1.w;
            float4 u0 = *(const float4*)&Bs[kk * 132 + tx * 8];
            float4 u1 = *(const float4*)&Bs[kk * 132 + tx * 8 + 4];
            b[0]=u0.x; b[1]=u0.y; b[2]=u0.z; b[3]=u0.w;
            b[4]=u1.x; b[5]=u1.y; b[6]=u1.z; b[7]=u1.w;
#pragma unroll
            for (int i = 0; i < 8; i++)
#pragma unroll
                for (int j = 0; j < 8; j++)
                    acc[i][j] = fmaf(a[i], b[j], acc[i][j]);
        }

        // epilogue for this half
        int khs[8], kws[8];
#pragma unroll
        for (int j = 0; j < 8; j++) {
            int gn = n0 + tx * 8 + j;
            int kh = gn / WS_;
            khs[j] = kh;
            kws[j] = gn - kh * WS_;
        }
#pragma unroll
        for (int i = 0; i < 8; i++) {
            int gm = m0 + ty * 8 + i;
            if (gm >= NTOK) continue;
            int lrow = ty * 8 + i;
            float* srow = g_s + (size_t)bh * NN_ + gm * NTOK;
#pragma unroll
            for (int j = 0; j < 8; j++) {
                int gn = n0 + tx * 8 + j;
                if (gn >= NTOK) continue;
                srow[gn] = acc[i][j] * 0.125f
                         + relh[lrow * 16 + khs[j]]
                         + relw[lrow * 16 + kws[j]];
            }
        }
        __syncthreads();   // before restaging Bs for next half
    }
}

// =====================================================================
// softmax: one warp per row of 196  (passing round-12 version)
// =====================================================================
__global__ __launch_bounds__(128)
void softmax_kernel()
{
    const int lane = threadIdx.x & 31;
    const size_t row = (size_t)blockIdx.x * 4 + (threadIdx.x >> 5);
    float* s = g_s + row * NTOK;

    float v[7];
    float mx = -INFINITY;
#pragma unroll
    for (int t = 0; t < 7; t++) {
        int j = lane + 32 * t;
        v[t] = (j < NTOK) ? s[j] : -INFINITY;
        mx = fmaxf(mx, v[t]);
    }
#pragma unroll
    for (int off = 16; off > 0; off >>= 1)
        mx = fmaxf(mx, __shfl_xor_sync(0xffffffffu, mx, off));
    float sum = 0.f;
#pragma unroll
    for (int t = 0; t < 7; t++) {
        int j = lane + 32 * t;
        if (j < NTOK) {
            float e = __expf(v[t] - mx);
            v[t] = e;
            sum += e;
        }
    }
#pragma unroll
    for (int off = 16; off > 0; off >>= 1)
        sum += __shfl_xor_sync(0xffffffffu, sum, off);
    float inv = 1.f / sum;
#pragma unroll
    for (int t = 0; t < 7; t++) {
        int j = lane + 32 * t;
        if (j < NTOK) s[j] = v[t] * inv;
    }
}

// =====================================================================
// AV GEMM (passing round-12 version)
// =====================================================================
__global__ __launch_bounds__(256)
void av_gemm()
{
    __shared__ float As[2][16][132];
    __shared__ float Bs[2][16][68];
    const int tid = threadIdx.x;
    const int bh = blockIdx.z;
    const int m0 = blockIdx.x * 128;
    const int tx = tid & 7;
    const int ty = tid >> 3;
    const float* P = g_s + (size_t)bh * NN_;
    const float* V = g_v + bh * (NTOK * HD_);
    const int wdw = bh / NH_, hh = bh - wdw * NH_;

    float acc[4][8];
#pragma unroll
    for (int i = 0; i < 4; i++)
#pragma unroll
        for (int j = 0; j < 8; j++) acc[i][j] = 0.f;

    const int NC = 13;
    float4 pa[2], pb;

#pragma unroll
    for (int i = 0; i < 2; i++) {
        int lin = tid + 256 * i;
        int row = lin >> 2;
        int kq  = (lin & 3) * 4;
        pa[i] = make_float4(0.f, 0.f, 0.f, 0.f);
        if (m0 + row < NTOK && kq < NTOK)
            pa[i] = *(const float4*)(P + (m0 + row) * NTOK + kq);
    }
    {
        int vrow = tid >> 4;
        int c4   = (tid & 15) * 4;
        pb = make_float4(0.f, 0.f, 0.f, 0.f);
        if (vrow < NTOK) pb = *(const float4*)(V + vrow * HD_ + c4);
    }
#pragma unroll
    for (int i = 0; i < 2; i++) {
        int lin = tid + 256 * i;
        int row = lin >> 2;
        int kq  = (lin & 3) * 4;
        As[0][kq + 0][row] = pa[i].x; As[0][kq + 1][row] = pa[i].y;
        As[0][kq + 2][row] = pa[i].z; As[0][kq + 3][row] = pa[i].w;
    }
    {
        int vrow = tid >> 4;
        int c4   = (tid & 15) * 4;
        *(float4*)&Bs[0][vrow][c4] = pb;
    }
    __syncthreads();

    for (int c = 0; c < NC; c++) {
        if (c + 1 < NC) {
            int k0 = (c + 1) * 16;
#pragma unroll
            for (int i = 0; i < 2; i++) {
                int lin = tid + 256 * i;
                int row = lin >> 2;
                int kq  = (lin & 3) * 4;
                pa[i] = make_float4(0.f, 0.f, 0.f, 0.f);
                if (m0 + row < NTOK && k0 + kq < NTOK)
                    pa[i] = *(const float4*)(P + (m0 + row) * NTOK + k0 + kq);
            }
            int vrow = tid >> 4;
            int c4   = (tid & 15) * 4;
            pb = make_float4(0.f, 0.f, 0.f, 0.f);
            if (k0 + vrow < NTOK) pb = *(const float4*)(V + (k0 + vrow) * HD_ + c4);
        }
        const int buf = c & 1;
#pragma unroll
        for (int kk = 0; kk < 16; kk++) {
            float a[4], b[8];
            float4 t0 = *(const float4*)&As[buf][kk][ty * 4];
            a[0]=t0.x; a[1]=t0.y; a[2]=t0.z; a[3]=t0.w;
            float4 u0 = *(const float4*)&Bs[buf][kk][tx * 8];
            float4 u1 = *(const float4*)&Bs[buf][kk][tx * 8 + 4];
            b[0]=u0.x; b[1]=u0.y; b[2]=u0.z; b[3]=u0.w;
            b[4]=u1.x; b[5]=u1.y; b[6]=u1.z; b[7]=u1.w;
#pragma unroll
            for (int i = 0; i < 4; i++)
#pragma unroll
                for (int j = 0; j < 8; j++)
                    acc[i][j] = fmaf(a[i], b[j], acc[i][j]);
        }
        if (c + 1 < NC) {
            const int nb = (c + 1) & 1;
#pragma unroll
            for (int i = 0; i < 2; i++) {
                int lin = tid + 256 * i;
                int row = lin >> 2;
                int kq  = (lin & 3) * 4;
                As[nb][kq + 0][row] = pa[i].x; As[nb][kq + 1][row] = pa[i].y;
                As[nb][kq + 2][row] = pa[i].z; As[nb][kq + 3][row] = pa[i].w;
            }
            int vrow = tid >> 4;
            int c4   = (tid & 15) * 4;
            *(float4*)&Bs[nb][vrow][c4] = pb;
        }
        __syncthreads();
    }

#pragma unroll
    for (int i = 0; i < 4; i++) {
        int gm = m0 + ty * 4 + i;
        if (gm >= NTOK) continue;
        float* orow = g_ao + (size_t)(wdw * NTOK + gm) * DIM_ + hh * HD_ + tx * 8;
        orow[0] = acc[i][0]; orow[1] = acc[i][1];
        orow[2] = acc[i][2]; orow[3] = acc[i][3];
        orow[4] = acc[i][4]; orow[5] = acc[i][5];
        orow[6] = acc[i][6]; orow[7] = acc[i][7];
    }
}

// =====================================================================
// GEMM 2: out = g_ao @ proj_w^T + proj_b  (passing round-12 version)
// =====================================================================
__global__ __launch_bounds__(256)
void proj_gemm(const float* __restrict__ w, const float* __restrict__ bias,
               float* __restrict__ out)
{
    __shared__ float As[2][16][132];
    __shared__ float Bs[2][16][132];
    const int tid = threadIdx.x;
    const int m0 = blockIdx.x * 128;
    const int n0 = blockIdx.y * 128;
    const int tx = tid & 15;
    const int ty = tid >> 4;

    int abase[2];
#pragma unroll
    for (int i = 0; i < 2; i++) {
        int lin = tid + 256 * i;
        int row = lin >> 2;
        int gm  = m0 + row;
        abase[i] = (gm < MROWS) ? gm * DIM_ : -1;
    }

    float acc[8][8];
#pragma unroll
    for (int i = 0; i < 8; i++)
#pragma unroll
        for (int j = 0; j < 8; j++) acc[i][j] = 0.f;

    float4 pa[2], pb[2];
#pragma unroll
    for (int i = 0; i < 2; i++) {
        int lin = tid + 256 * i;
        int kq  = (lin & 3) * 4;
        pa[i] = make_float4(0.f, 0.f, 0.f, 0.f);
        if (abase[i] >= 0) pa[i] = *(const float4*)(g_ao + abase[i] + kq);
        int row = lin >> 2;
        pb[i] = *(const float4*)(w + (n0 + row) * DIM_ + kq);
    }
#pragma unroll
    for (int i = 0; i < 2; i++) {
        int lin = tid + 256 * i;
        int row = lin >> 2;
        int kq  = (lin & 3) * 4;
        As[0][kq + 0][row] = pa[i].x; As[0][kq + 1][row] = pa[i].y;
        As[0][kq + 2][row] = pa[i].z; As[0][kq + 3][row] = pa[i].w;
        Bs[0][kq + 0][row] = pb[i].x; Bs[0][kq + 1][row] = pb[i].y;
        Bs[0][kq + 2][row] = pb[i].z; Bs[0][kq + 3][row] = pb[i].w;
    }
    __syncthreads();

    const int NK = DIM_ / 16;
    for (int c = 0; c < NK; c++) {
        if (c + 1 < NK) {
            int k0 = (c + 1) * 16;
#pragma unroll
            for (int i = 0; i < 2; i++) {
                int lin = tid + 256 * i;
                int kq  = (lin & 3) * 4;
                pa[i] = make_float4(0.f, 0.f, 0.f, 0.f);
                if (abase[i] >= 0) pa[i] = *(const float4*)(g_ao + abase[i] + k0 + kq);
                int row = lin >> 2;
                pb[i] = *(const float4*)(w + (n0 + row) * DIM_ + k0 + kq);
            }
        }
        const int buf = c & 1;
#pragma unroll
        for (int kk = 0; kk < 16; kk++) {
            float a[8], b[8];
            float4 t0 = *(const float4*)&As[buf][kk][ty * 8];
            float4 t1 = *(const float4*)&As[buf][kk][ty * 8 + 4];
            a[0]=t0.x; a[1]=t0.y; a[2]=t0.z; a[3]=t0.w;
            a[4]=t1.x; a[5]=t1.y; a[6]=t1.z; a[7]=t1.w;
            float4 u0 = *(const float4*)&Bs[buf][kk][tx * 8];
            float4 u1 = *(const float4*)&Bs[buf][kk][tx * 8 + 4];
            b[0]=u0.x; b[1]=u0.y; b[2]=u0.z; b[3]=u0.w;
            b[4]=u1.x; b[5]=u1.y; b[6]=u1.z; b[7]=u1.w;
#pragma unroll
            for (int i = 0; i < 8; i++)
#pragma unroll
                for (int j = 0; j < 8; j++)
                    acc[i][j] = fmaf(a[i], b[j], acc[i][j]);
        }
        if (c + 1 < NK) {
            const int nb = (c + 1) & 1;
#pragma unroll
            for (int i = 0; i < 2; i++) {
                int lin = tid + 256 * i;
                int row = lin >> 2;
                int kq  = (lin & 3) * 4;
                As[nb][kq + 0][row] = pa[i].x; As[nb][kq + 1][row] = pa[i].y;
                As[nb][kq + 2][row] = pa[i].z; As[nb][kq + 3][row] = pa[i].w;
                Bs[nb][kq + 0][row] = pb[i].x; Bs[nb][kq + 1][row] = pb[i].y;
                Bs[nb][kq + 2][row] = pb[i].z; Bs[nb][kq + 3][row] = pb[i].w;
            }
        }
        __syncthreads();
    }

#pragma unroll
    for (int i = 0; i < 8; i++) {
        int gm = m0 + ty * 8 + i;
        if (gm >= MROWS) continue;
        int wdw = gm / NTOK, t = gm - wdw * NTOK;
        int b  = wdw / 25,  wi = wdw - b * 25;
        int wh = wi / 5,    ww = wi - wh * 5;
        int th = t / WS_,   tw = t - th * WS_;
        int y  = wh * WS_ + th;
        int xc = ww * WS_ + tw;
        if (y >= IMGHW || xc >= IMGHW) continue;
        float* orow = out + ((b * IMGHW + y) * IMGHW + xc) * DIM_;
#pragma unroll
        for (int j = 0; j < 8; j++) {
            int gn = n0 + tx * 8 + j;
            orow[gn] = acc[i][j] + bias[gn];
        }
    }
}

// =====================================================================
extern "C" void kernel_launch(void* const* d_in, const int* in_sizes, int n_in,
                              void* d_out, int out_size)
{
    const float* x      = (const float*)d_in[0];
    const float* qkv_w  = (const float*)d_in[1];
    const float* qkv_b  = (const float*)d_in[2];
    const float* proj_w = (const float*)d_in[3];
    const float* proj_b = (const float*)d_in[4];
    const float* rph    = (const float*)d_in[5];
    const float* rpw    = (const float*)d_in[6];
    float* out = (float*)d_out;

    cudaFuncSetAttribute(scores_gemm,
                         cudaFuncAttributeMaxDynamicSharedMemorySize,
                         SC_SMEM_BYTES);

    dim3 g1((MROWS + 127) / 128, QKV_N / 128);
    qkv_gemm<<<g1, 256>>>(x, qkv_w, qkv_b);

    dim3 gs(2, BH_);
    scores_gemm<<<gs, 256, SC_SMEM_BYTES>>>(rph, rpw);

    softmax_kernel<<<(BH_ * NTOK) / 4, 128>>>();

    dim3 ga(2, 1, BH_);
    av_gemm<<<ga, 256>>>();

    dim3 g2((MROWS + 127) / 128, DIM_ / 128);
    proj_gemm<<<g2, 256>>>(proj_w, proj_b, out);
}

// round 14
// speedup vs baseline: 1.6669x; 1.2529x over previous
#include <cuda_runtime.h>
#include <math.h>

#define WS_      14
#define NTOK     196
#define NH_      12
#define HD_      64
#define DIM_     768
#define NWIN     200
#define BH_      2400
#define MROWS    39200
#define IMGHW    64
#define QKV_N    2304
#define NN_      38416   // 196*196

// ---- scratch ----
__device__ float g_q   [BH_ * NTOK * HD_];
__device__ float g_k   [BH_ * NTOK * HD_];
__device__ float g_v   [BH_ * NTOK * HD_];
__device__ float g_ao  [MROWS * DIM_];
__device__ float g_s   [BH_ * NN_];      // scores / probs (369 MB)

// =====================================================================
// GEMM 1: qkv = gather(x) @ qkv_w^T + qkv_b  (passing round-13 version)
// =====================================================================
__global__ __launch_bounds__(256)
void qkv_gemm(const float* __restrict__ x, const float* __restrict__ w,
              const float* __restrict__ bias)
{
    __shared__ float As[2][16][132];
    __shared__ float Bs[2][16][132];
    const int tid = threadIdx.x;
    const int m0 = blockIdx.x * 128;
    const int n0 = blockIdx.y * 128;
    const int tx = tid & 15;
    const int ty = tid >> 4;

    int abase[2];
#pragma unroll
    for (int i = 0; i < 2; i++) {
        int lin = tid + 256 * i;
        int row = lin >> 2;
        int gm  = m0 + row;
        int base = -1;
        if (gm < MROWS) {
            int wdw = gm / NTOK, t = gm - wdw * NTOK;
            int b  = wdw / 25,  wi = wdw - b * 25;
            int wh = wi / 5,    ww = wi - wh * 5;
            int th = t / WS_,   tw = t - th * WS_;
            int y  = wh * WS_ + th;
            int xc = ww * WS_ + tw;
            if (y < IMGHW && xc < IMGHW)
                base = ((b * IMGHW + y) * IMGHW + xc) * DIM_;
        }
        abase[i] = base;
    }

    float acc[8][8];
#pragma unroll
    for (int i = 0; i < 8; i++)
#pragma unroll
        for (int j = 0; j < 8; j++) acc[i][j] = 0.f;

    float4 pa[2], pb[2];
#pragma unroll
    for (int i = 0; i < 2; i++) {
        int lin = tid + 256 * i;
        int kq  = (lin & 3) * 4;
        pa[i] = make_float4(0.f, 0.f, 0.f, 0.f);
        if (abase[i] >= 0) pa[i] = *(const float4*)(x + abase[i] + kq);
        int row = lin >> 2;
        pb[i] = *(const float4*)(w + (n0 + row) * DIM_ + kq);
    }
#pragma unroll
    for (int i = 0; i < 2; i++) {
        int lin = tid + 256 * i;
        int row = lin >> 2;
        int kq  = (lin & 3) * 4;
        As[0][kq + 0][row] = pa[i].x; As[0][kq + 1][row] = pa[i].y;
        As[0][kq + 2][row] = pa[i].z; As[0][kq + 3][row] = pa[i].w;
        Bs[0][kq + 0][row] = pb[i].x; Bs[0][kq + 1][row] = pb[i].y;
        Bs[0][kq + 2][row] = pb[i].z; Bs[0][kq + 3][row] = pb[i].w;
    }
    __syncthreads();

    const int NK = DIM_ / 16;
    for (int c = 0; c < NK; c++) {
        if (c + 1 < NK) {
            int k0 = (c + 1) * 16;
#pragma unroll
            for (int i = 0; i < 2; i++) {
                int lin = tid + 256 * i;
                int kq  = (lin & 3) * 4;
                pa[i] = make_float4(0.f, 0.f, 0.f, 0.f);
                if (abase[i] >= 0) pa[i] = *(const float4*)(x + abase[i] + k0 + kq);
                int row = lin >> 2;
                pb[i] = *(const float4*)(w + (n0 + row) * DIM_ + k0 + kq);
            }
        }
        const int buf = c & 1;
#pragma unroll
        for (int kk = 0; kk < 16; kk++) {
            float a[8], b[8];
            float4 t0 = *(const float4*)&As[buf][kk][ty * 8];
            float4 t1 = *(const float4*)&As[buf][kk][ty * 8 + 4];
            a[0]=t0.x; a[1]=t0.y; a[2]=t0.z; a[3]=t0.w;
            a[4]=t1.x; a[5]=t1.y; a[6]=t1.z; a[7]=t1.w;
            float4 u0 = *(const float4*)&Bs[buf][kk][tx * 8];
            float4 u1 = *(const float4*)&Bs[buf][kk][tx * 8 + 4];
            b[0]=u0.x; b[1]=u0.y; b[2]=u0.z; b[3]=u0.w;
            b[4]=u1.x; b[5]=u1.y; b[6]=u1.z; b[7]=u1.w;
#pragma unroll
            for (int i = 0; i < 8; i++)
#pragma unroll
                for (int j = 0; j < 8; j++)
                    acc[i][j] = fmaf(a[i], b[j], acc[i][j]);
        }
        if (c + 1 < NK) {
            const int nb = (c + 1) & 1;
#pragma unroll
            for (int i = 0; i < 2; i++) {
                int lin = tid + 256 * i;
                int row = lin >> 2;
                int kq  = (lin & 3) * 4;
                As[nb][kq + 0][row] = pa[i].x; As[nb][kq + 1][row] = pa[i].y;
                As[nb][kq + 2][row] = pa[i].z; As[nb][kq + 3][row] = pa[i].w;
                Bs[nb][kq + 0][row] = pb[i].x; Bs[nb][kq + 1][row] = pb[i].y;
                Bs[nb][kq + 2][row] = pb[i].z; Bs[nb][kq + 3][row] = pb[i].w;
            }
        }
        __syncthreads();
    }

#pragma unroll
    for (int i = 0; i < 8; i++) {
        int gm = m0 + ty * 8 + i;
        if (gm >= MROWS) continue;
        int wdw = gm / NTOK, t = gm - wdw * NTOK;
#pragma unroll
        for (int j = 0; j < 8; j++) {
            int gn = n0 + tx * 8 + j;
            float c = acc[i][j] + bias[gn];
            int which = gn / DIM_;
            int r = gn - which * DIM_;
            int h = r >> 6, d = r & 63;
            int idx = ((wdw * NH_ + h) * NTOK + t) * HD_ + d;
            float* dst = (which == 0) ? g_q : ((which == 1) ? g_k : g_v);
            dst[idx] = c;
        }
    }
}

// =====================================================================
// scores v3: rel-as-GEMM + gather.
// grid (2, BH_), block 256.
// smem layout (floats):
//   As [64][132]  Q tile transposed                      (8448)
//   Th [128][29], Tw [128][29]  rel dot tables           (7424)
//   Bs [64][132]  K half-tile transposed  -- region also
//                 used first for rph/rpw staging (stride 65)
// =====================================================================
#define SC_SMEM_FLOATS (8448 + 7424 + 8448)
#define SC_SMEM_BYTES  (SC_SMEM_FLOATS * 4)
#define NREL 27   // 2*WS_-1

__global__ __launch_bounds__(256)
void scores_gemm(const float* __restrict__ rph, const float* __restrict__ rpw)
{
    extern __shared__ float sm[];
    float* As  = sm;               // [64][132]
    float* Th  = As + 8448;        // [128][29]
    float* Tw  = Th + 3712;        // [128][29]
    float* Bs  = Tw + 3712;        // [64][132]  (tables staged here first)
    float* tbl = Bs;               // rph: [27][65] at 0, rpw at +1755

    const int tid = threadIdx.x;
    const int bh  = blockIdx.y;
    const int m0  = blockIdx.x * 128;
    const int tx  = tid & 15;
    const int ty  = tid >> 4;
    const float* Q = g_q + bh * (NTOK * HD_);
    const float* K = g_k + bh * (NTOK * HD_);

    // ---- stage Q tile transposed + rel tables ----
#pragma unroll
    for (int i = 0; i < 8; i++) {
        int e = tid + 256 * i;
        int row = e >> 4;
        int d0  = (e & 15) * 4;
        float4 v = make_float4(0.f, 0.f, 0.f, 0.f);
        if (m0 + row < NTOK) v = *(const float4*)(Q + (m0 + row) * HD_ + d0);
        As[(d0 + 0) * 132 + row] = v.x;
        As[(d0 + 1) * 132 + row] = v.y;
        As[(d0 + 2) * 132 + row] = v.z;
        As[(d0 + 3) * 132 + row] = v.w;
    }
    for (int i = tid; i < 2 * NREL * HD_; i += 256) {
        int isW = (i >= NREL * HD_);
        int l = isW ? i - NREL * HD_ : i;
        int r = l >> 6, d = l & 63;
        tbl[(isW ? 1755 : 0) + r * 65 + d] = __ldg((isW ? rpw : rph) + r * HD_ + d);
    }
    __syncthreads();

    // ---- T = Q_tile @ table^T   (128 x 27, both tables) ----
    {
        const int ty2 = tid >> 3;        // 0..31 -> rows ty2*4..+3
        const int tx2 = tid & 7;         // cols tx2*4..+3 (guard < 27)
#pragma unroll
        for (int tb = 0; tb < 2; tb++) {
            const float* tb_base = tbl + (tb ? 1755 : 0);
            float* Tout = tb ? Tw : Th;
            float t[4][4];
#pragma unroll
            for (int i = 0; i < 4; i++)
#pragma unroll
                for (int j = 0; j < 4; j++) t[i][j] = 0.f;
#pragma unroll 8
            for (int d = 0; d < HD_; d++) {
                float qv[4], tv[4];
#pragma unroll
                for (int i = 0; i < 4; i++)
                    qv[i] = As[d * 132 + ty2 * 4 + i];
#pragma unroll
                for (int j = 0; j < 4; j++) {
                    int col = tx2 * 4 + j;
                    tv[j] = tb_base[(col < NREL ? col : 0) * 65 + d];
                }
#pragma unroll
                for (int i = 0; i < 4; i++)
#pragma unroll
                    for (int j = 0; j < 4; j++)
                        t[i][j] = fmaf(qv[i], tv[j], t[i][j]);
            }
#pragma unroll
            for (int j = 0; j < 4; j++) {
                int col = tx2 * 4 + j;
                if (col < NREL) {
#pragma unroll
                    for (int i = 0; i < 4; i++)
                        Tout[(ty2 * 4 + i) * 29 + col] = t[i][j];
                }
            }
        }
    }
    __syncthreads();   // T done; tables region free for Bs

    for (int half = 0; half < 2; half++) {
        const int n0 = half * 128;
#pragma unroll
        for (int i = 0; i < 8; i++) {
            int e = tid + 256 * i;
            int row = e >> 4;
            int d0  = (e & 15) * 4;
            float4 v = make_float4(0.f, 0.f, 0.f, 0.f);
            if (n0 + row < NTOK) v = *(const float4*)(K + (n0 + row) * HD_ + d0);
            Bs[(d0 + 0) * 132 + row] = v.x;
            Bs[(d0 + 1) * 132 + row] = v.y;
            Bs[(d0 + 2) * 132 + row] = v.z;
            Bs[(d0 + 3) * 132 + row] = v.w;
        }
        __syncthreads();

        float acc[8][8];
#pragma unroll
        for (int i = 0; i < 8; i++)
#pragma unroll
            for (int j = 0; j < 8; j++) acc[i][j] = 0.f;

#pragma unroll 8
        for (int kk = 0; kk < HD_; kk++) {
            float a[8], b[8];
            float4 t0 = *(const float4*)&As[kk * 132 + ty * 8];
            float4 t1 = *(const float4*)&As[kk * 132 + ty * 8 + 4];
            a[0]=t0.x; a[1]=t0.y; a[2]=t0.z; a[3]=t0.w;
            a[4]=t1.x; a[5]=t1.y; a[6]=t1.z; a[7]=t1.w;
            float4 u0 = *(const float4*)&Bs[kk * 132 + tx * 8];
            float4 u1 = *(const float4*)&Bs[kk * 132 + tx * 8 + 4];
            b[0]=u0.x; b[1]=u0.y; b[2]=u0.z; b[3]=u0.w;
            b[4]=u1.x; b[5]=u1.y; b[6]=u1.z; b[7]=u1.w;
#pragma unroll
            for (int i = 0; i < 8; i++)
#pragma unroll
                for (int j = 0; j < 8; j++)
                    acc[i][j] = fmaf(a[i], b[j], acc[i][j]);
        }

        int khs[8], kws[8];
#pragma unroll
        for (int j = 0; j < 8; j++) {
            int gn = n0 + tx * 8 + j;
            int kh = gn / WS_;
            khs[j] = kh;
            kws[j] = gn - kh * WS_;
        }
#pragma unroll
        for (int i = 0; i < 8; i++) {
            int gm = m0 + ty * 8 + i;
            if (gm >= NTOK) continue;
            int lrow = ty * 8 + i;
            int qh  = gm / WS_;
            int qwc = gm - qh * WS_;
            float* srow = g_s + (size_t)bh * NN_ + gm * NTOK;
            const float* thr = Th + lrow * 29 + (qh + WS_ - 1);
            const float* twr = Tw + lrow * 29 + (qwc + WS_ - 1);
#pragma unroll
            for (int j = 0; j < 8; j++) {
                int gn = n0 + tx * 8 + j;
                if (gn >= NTOK) continue;
                srow[gn] = acc[i][j] * 0.125f + thr[-khs[j]] + twr[-kws[j]];
            }
        }
        __syncthreads();
    }
}

// =====================================================================
// softmax: one warp per row of 196  (passing version)
// =====================================================================
__global__ __launch_bounds__(128)
void softmax_kernel()
{
    const int lane = threadIdx.x & 31;
    const size_t row = (size_t)blockIdx.x * 4 + (threadIdx.x >> 5);
    float* s = g_s + row * NTOK;

    float v[7];
    float mx = -INFINITY;
#pragma unroll
    for (int t = 0; t < 7; t++) {
        int j = lane + 32 * t;
        v[t] = (j < NTOK) ? s[j] : -INFINITY;
        mx = fmaxf(mx, v[t]);
    }
#pragma unroll
    for (int off = 16; off > 0; off >>= 1)
        mx = fmaxf(mx, __shfl_xor_sync(0xffffffffu, mx, off));
    float sum = 0.f;
#pragma unroll
    for (int t = 0; t < 7; t++) {
        int j = lane + 32 * t;
        if (j < NTOK) {
            float e = __expf(v[t] - mx);
            v[t] = e;
            sum += e;
        }
    }
#pragma unroll
    for (int off = 16; off > 0; off >>= 1)
        sum += __shfl_xor_sync(0xffffffffu, sum, off);
    float inv = 1.f / sum;
#pragma unroll
    for (int t = 0; t < 7; t++) {
        int j = lane + 32 * t;
        if (j < NTOK) s[j] = v[t] * inv;
    }
}

// =====================================================================
// av v2: one CTA per bh, 256 threads, 8x8 microtile (32 ty x 8 tx).
// V staged once [208][68] (zero-padded); P chunks double-buffered
// As[2][16][260] with register prefetch.
// =====================================================================
#define AV_SMEM_FLOATS (208 * 68 + 2 * 16 * 260)
#define AV_SMEM_BYTES  (AV_SMEM_FLOATS * 4)

__global__ __launch_bounds__(256)
void av_gemm()
{
    extern __shared__ float sm[];
    float* Vs = sm;                 // [208][68]
    float* Ab = Vs + 208 * 68;      // [2][16][260]

    const int tid = threadIdx.x;
    const int bh  = blockIdx.x;
    const int tx  = tid & 7;        // cols tx*8..+7
    const int ty  = tid >> 3;       // rows ty*8..+7 (0..255)
    const float* P = g_s + (size_t)bh * NN_;
    const float* V = g_v + bh * (NTOK * HD_);
    const int wdw = bh / NH_, hh = bh - wdw * NH_;

    // ---- stage V (zero-padded to 208 rows) ----
    for (int i = tid; i < 208 * 16; i += 256) {
        int row = i >> 4;
        int c4  = (i & 15) * 4;
        float4 v = make_float4(0.f, 0.f, 0.f, 0.f);
        if (row < NTOK) v = *(const float4*)(V + row * HD_ + c4);
        *(float4*)&Vs[row * 68 + c4] = v;
    }

    float acc[8][8];
#pragma unroll
    for (int i = 0; i < 8; i++)
#pragma unroll
        for (int j = 0; j < 8; j++) acc[i][j] = 0.f;

    const int NC = 13;   // 196 = 12*16 + 4
    float4 pa[4];

    // prologue: P chunk 0 -> regs -> buf 0
#pragma unroll
    for (int i = 0; i < 4; i++) {
        int lin = tid + 256 * i;
        int row = lin >> 2;
        int kq  = (lin & 3) * 4;
        pa[i] = make_float4(0.f, 0.f, 0.f, 0.f);
        if (row < NTOK) pa[i] = *(const float4*)(P + row * NTOK + kq);
    }
#pragma unroll
    for (int i = 0; i < 4; i++) {
        int lin = tid + 256 * i;
        int row = lin >> 2;
        int kq  = (lin & 3) * 4;
        Ab[(kq + 0) * 260 + row] = pa[i].x;
        Ab[(kq + 1) * 260 + row] = pa[i].y;
        Ab[(kq + 2) * 260 + row] = pa[i].z;
        Ab[(kq + 3) * 260 + row] = pa[i].w;
    }
    __syncthreads();

    for (int c = 0; c < NC; c++) {
        if (c + 1 < NC) {
            int k0 = (c + 1) * 16;
#pragma unroll
            for (int i = 0; i < 4; i++) {
                int lin = tid + 256 * i;
                int row = lin >> 2;
                int kq  = (lin & 3) * 4;
                pa[i] = make_float4(0.f, 0.f, 0.f, 0.f);
                if (row < NTOK && (k0 + kq) < NTOK)
                    pa[i] = *(const float4*)(P + row * NTOK + k0 + kq);
            }
        }
        const float* Ac = Ab + (c & 1) * 4160;
        const float* Vc = Vs + c * 16 * 68;
#pragma unroll
        for (int kk = 0; kk < 16; kk++) {
            float a[8], b[8];
            float4 t0 = *(const float4*)&Ac[kk * 260 + ty * 8];
            float4 t1 = *(const float4*)&Ac[kk * 260 + ty * 8 + 4];
            a[0]=t0.x; a[1]=t0.y; a[2]=t0.z; a[3]=t0.w;
            a[4]=t1.x; a[5]=t1.y; a[6]=t1.z; a[7]=t1.w;
            float4 u0 = *(const float4*)&Vc[kk * 68 + tx * 8];
            float4 u1 = *(const float4*)&Vc[kk * 68 + tx * 8 + 4];
            b[0]=u0.x; b[1]=u0.y; b[2]=u0.z; b[3]=u0.w;
            b[4]=u1.x; b[5]=u1.y; b[6]=u1.z; b[7]=u1.w;
#pragma unroll
            for (int i = 0; i < 8; i++)
#pragma unroll
                for (int j = 0; j < 8; j++)
                    acc[i][j] = fmaf(a[i], b[j], acc[i][j]);
        }
        if (c + 1 < NC) {
            float* An = Ab + ((c + 1) & 1) * 4160;
#pragma unroll
            for (int i = 0; i < 4; i++) {
                int lin = tid + 256 * i;
                int row = lin >> 2;
                int kq  = (lin & 3) * 4;
                An[(kq + 0) * 260 + row] = pa[i].x;
                An[(kq + 1) * 260 + row] = pa[i].y;
                An[(kq + 2) * 260 + row] = pa[i].z;
                An[(kq + 3) * 260 + row] = pa[i].w;
            }
        }
        __syncthreads();
    }

    // epilogue
#pragma unroll
    for (int i = 0; i < 8; i++) {
        int gm = ty * 8 + i;
        if (gm >= NTOK) continue;
        float* orow = g_ao + (size_t)(wdw * NTOK + gm) * DIM_ + hh * HD_ + tx * 8;
        *(float4*)orow       = make_float4(acc[i][0], acc[i][1], acc[i][2], acc[i][3]);
        *(float4*)(orow + 4) = make_float4(acc[i][4], acc[i][5], acc[i][6], acc[i][7]);
    }
}

// =====================================================================
// GEMM 2: out = g_ao @ proj_w^T + proj_b  (passing round-13 version)
// =====================================================================
__global__ __launch_bounds__(256)
void proj_gemm(const float* __restrict__ w, const float* __restrict__ bias,
               float* __restrict__ out)
{
    __shared__ float As[2][16][132];
    __shared__ float Bs[2][16][132];
    const int tid = threadIdx.x;
    const int m0 = blockIdx.x * 128;
    const int n0 = blockIdx.y * 128;
    const int tx = tid & 15;
    const int ty = tid >> 4;

    int abase[2];
#pragma unroll
    for (int i = 0; i < 2; i++) {
        int lin = tid + 256 * i;
        int row = lin >> 2;
        int gm  = m0 + row;
        abase[i] = (gm < MROWS) ? gm * DIM_ : -1;
    }

    float acc[8][8];
#pragma unroll
    for (int i = 0; i < 8; i++)
#pragma unroll
        for (int j = 0; j < 8; j++) acc[i][j] = 0.f;

    float4 pa[2], pb[2];
#pragma unroll
    for (int i = 0; i < 2; i++) {
        int lin = tid + 256 * i;
        int kq  = (lin & 3) * 4;
        pa[i] = make_float4(0.f, 0.f, 0.f, 0.f);
        if (abase[i] >= 0) pa[i] = *(const float4*)(g_ao + abase[i] + kq);
        int row = lin >> 2;
        pb[i] = *(const float4*)(w + (n0 + row) * DIM_ + kq);
    }
#pragma unroll
    for (int i = 0; i < 2; i++) {
        int lin = tid + 256 * i;
        int row = lin >> 2;
        int kq  = (lin & 3) * 4;
        As[0][kq + 0][row] = pa[i].x; As[0][kq + 1][row] = pa[i].y;
        As[0][kq + 2][row] = pa[i].z; As[0][kq + 3][row] = pa[i].w;
        Bs[0][kq + 0][row] = pb[i].x; Bs[0][kq + 1][row] = pb[i].y;
        Bs[0][kq + 2][row] = pb[i].z; Bs[0][kq + 3][row] = pb[i].w;
    }
    __syncthreads();

    const int NK = DIM_ / 16;
    for (int c = 0; c < NK; c++) {
        if (c + 1 < NK) {
            int k0 = (c + 1) * 16;
#pragma unroll
            for (int i = 0; i < 2; i++) {
                int lin = tid + 256 * i;
                int kq  = (lin & 3) * 4;
                pa[i] = make_float4(0.f, 0.f, 0.f, 0.f);
                if (abase[i] >= 0) pa[i] = *(const float4*)(g_ao + abase[i] + k0 + kq);
                int row = lin >> 2;
                pb[i] = *(const float4*)(w + (n0 + row) * DIM_ + k0 + kq);
            }
        }
        const int buf = c & 1;
#pragma unroll
        for (int kk = 0; kk < 16; kk++) {
            float a[8], b[8];
            float4 t0 = *(const float4*)&As[buf][kk][ty * 8];
            float4 t1 = *(const float4*)&As[buf][kk][ty * 8 + 4];
            a[0]=t0.x; a[1]=t0.y; a[2]=t0.z; a[3]=t0.w;
            a[4]=t1.x; a[5]=t1.y; a[6]=t1.z; a[7]=t1.w;
            float4 u0 = *(const float4*)&Bs[buf][kk][tx * 8];
            float4 u1 = *(const float4*)&Bs[buf][kk][tx * 8 + 4];
            b[0]=u0.x; b[1]=u0.y; b[2]=u0.z; b[3]=u0.w;
            b[4]=u1.x; b[5]=u1.y; b[6]=u1.z; b[7]=u1.w;
#pragma unroll
            for (int i = 0; i < 8; i++)
#pragma unroll
                for (int j = 0; j < 8; j++)
                    acc[i][j] = fmaf(a[i], b[j], acc[i][j]);
        }
        if (c + 1 < NK) {
            const int nb = (c + 1) & 1;
#pragma unroll
            for (int i = 0; i < 2; i++) {
                int lin = tid + 256 * i;
                int row = lin >> 2;
                int kq  = (lin & 3) * 4;
                As[nb][kq + 0][row] = pa[i].x; As[nb][kq + 1][row] = pa[i].y;
                As[nb][kq + 2][row] = pa[i].z; As[nb][kq + 3][row] = pa[i].w;
                Bs[nb][kq + 0][row] = pb[i].x; Bs[nb][kq + 1][row] = pb[i].y;
                Bs[nb][kq + 2][row] = pb[i].z; Bs[nb][kq + 3][row] = pb[i].w;
            }
        }
        __syncthreads();
    }

#pragma unroll
    for (int i = 0; i < 8; i++) {
        int gm = m0 + ty * 8 + i;
        if (gm >= MROWS) continue;
        int wdw = gm / NTOK, t = gm - wdw * NTOK;
        int b  = wdw / 25,  wi = wdw - b * 25;
        int wh = wi / 5,    ww = wi - wh * 5;
        int th = t / WS_,   tw = t - th * WS_;
        int y  = wh * WS_ + th;
        int xc = ww * WS_ + tw;
        if (y >= IMGHW || xc >= IMGHW) continue;
        float* orow = out + ((b * IMGHW + y) * IMGHW + xc) * DIM_;
#pragma unroll
        for (int j = 0; j < 8; j++) {
            int gn = n0 + tx * 8 + j;
            orow[gn] = acc[i][j] + bias[gn];
        }
    }
}

// =====================================================================
extern "C" void kernel_launch(void* const* d_in, const int* in_sizes, int n_in,
                              void* d_out, int out_size)
{
    const float* x      = (const float*)d_in[0];
    const float* qkv_w  = (const float*)d_in[1];
    const float* qkv_b  = (const float*)d_in[2];
    const float* proj_w = (const float*)d_in[3];
    const float* proj_b = (const float*)d_in[4];
    const float* rph    = (const float*)d_in[5];
    const float* rpw    = (const float*)d_in[6];
    float* out = (float*)d_out;

    cudaFuncSetAttribute(scores_gemm,
                         cudaFuncAttributeMaxDynamicSharedMemorySize, SC_SMEM_BYTES);
    cudaFuncSetAttribute(av_gemm,
                         cudaFuncAttributeMaxDynamicSharedMemorySize, AV_SMEM_BYTES);

    dim3 g1((MROWS + 127) / 128, QKV_N / 128);
    qkv_gemm<<<g1, 256>>>(x, qkv_w, qkv_b);

    dim3 gs(2, BH_);
    scores_gemm<<<gs, 256, SC_SMEM_BYTES>>>(rph, rpw);

    softmax_kernel<<<(BH_ * NTOK) / 4, 128>>>();

    av_gemm<<<BH_, 256, AV_SMEM_BYTES>>>();

    dim3 g2((MROWS + 127) / 128, DIM_ / 128);
    proj_gemm<<<g2, 256>>>(proj_w, proj_b, out);
}

// round 15
// speedup vs baseline: 1.6864x; 1.0117x over previous
#include <cuda_runtime.h>
#include <math.h>

#define WS_      14
#define NTOK     196
#define NH_      12
#define HD_      64
#define DIM_     768
#define NWIN     200
#define BH_      2400
#define MROWS    39200
#define IMGHW    64
#define QKV_N    2304
#define NN_      38416   // 196*196

// ---- scratch ----
__device__ float g_q   [BH_ * NTOK * HD_];
__device__ float g_k   [BH_ * NTOK * HD_];
__device__ float g_v   [BH_ * NTOK * HD_];
__device__ float g_ao  [MROWS * DIM_];
__device__ float g_s   [BH_ * NN_];      // scores / probs (369 MB)

// ---- packed f32x2 helpers (Blackwell base ISA) ----
__device__ __forceinline__ unsigned long long pk2(float x, float y) {
    unsigned long long r;
    asm("mov.b64 %0, {%1, %2};" : "=l"(r) : "f"(x), "f"(y));
    return r;
}
__device__ __forceinline__ void upk2(unsigned long long v, float& x, float& y) {
    asm("mov.b64 {%0, %1}, %2;" : "=f"(x), "=f"(y) : "l"(v));
}
#define FFMA2(C, A, B) \
    asm("fma.rn.f32x2 %0, %1, %2, %0;" : "+l"(C) : "l"(A), "l"(B))

// =====================================================================
// GEMM 1: qkv = gather(x) @ qkv_w^T + qkv_b  — f32x2 packed microkernel
// =====================================================================
__global__ __launch_bounds__(256)
void qkv_gemm(const float* __restrict__ x, const float* __restrict__ w,
              const float* __restrict__ bias)
{
    __shared__ float As[2][16][132];
    __shared__ float Bs[2][16][132];
    const int tid = threadIdx.x;
    const int m0 = blockIdx.x * 128;
    const int n0 = blockIdx.y * 128;
    const int tx = tid & 15;
    const int ty = tid >> 4;

    int abase[2];
#pragma unroll
    for (int i = 0; i < 2; i++) {
        int lin = tid + 256 * i;
        int row = lin >> 2;
        int gm  = m0 + row;
        int base = -1;
        if (gm < MROWS) {
            int wdw = gm / NTOK, t = gm - wdw * NTOK;
            int b  = wdw / 25,  wi = wdw - b * 25;
            int wh = wi / 5,    ww = wi - wh * 5;
            int th = t / WS_,   tw = t - th * WS_;
            int y  = wh * WS_ + th;
            int xc = ww * WS_ + tw;
            if (y < IMGHW && xc < IMGHW)
                base = ((b * IMGHW + y) * IMGHW + xc) * DIM_;
        }
        abase[i] = base;
    }

    unsigned long long acc[8][4];
#pragma unroll
    for (int i = 0; i < 8; i++)
#pragma unroll
        for (int j = 0; j < 4; j++) acc[i][j] = 0ULL;

    float4 pa[2], pb[2];
#pragma unroll
    for (int i = 0; i < 2; i++) {
        int lin = tid + 256 * i;
        int kq  = (lin & 3) * 4;
        pa[i] = make_float4(0.f, 0.f, 0.f, 0.f);
        if (abase[i] >= 0) pa[i] = *(const float4*)(x + abase[i] + kq);
        int row = lin >> 2;
        pb[i] = *(const float4*)(w + (n0 + row) * DIM_ + kq);
    }
#pragma unroll
    for (int i = 0; i < 2; i++) {
        int lin = tid + 256 * i;
        int row = lin >> 2;
        int kq  = (lin & 3) * 4;
        As[0][kq + 0][row] = pa[i].x; As[0][kq + 1][row] = pa[i].y;
        As[0][kq + 2][row] = pa[i].z; As[0][kq + 3][row] = pa[i].w;
        Bs[0][kq + 0][row] = pb[i].x; Bs[0][kq + 1][row] = pb[i].y;
        Bs[0][kq + 2][row] = pb[i].z; Bs[0][kq + 3][row] = pb[i].w;
    }
    __syncthreads();

    const int NK = DIM_ / 16;
    for (int c = 0; c < NK; c++) {
        if (c + 1 < NK) {
            int k0 = (c + 1) * 16;
#pragma unroll
            for (int i = 0; i < 2; i++) {
                int lin = tid + 256 * i;
                int kq  = (lin & 3) * 4;
                pa[i] = make_float4(0.f, 0.f, 0.f, 0.f);
                if (abase[i] >= 0) pa[i] = *(const float4*)(x + abase[i] + k0 + kq);
                int row = lin >> 2;
                pb[i] = *(const float4*)(w + (n0 + row) * DIM_ + k0 + kq);
            }
        }
        const int buf = c & 1;
#pragma unroll
        for (int kk = 0; kk < 16; kk++) {
            float4 t0 = *(const float4*)&As[buf][kk][ty * 8];
            float4 t1 = *(const float4*)&As[buf][kk][ty * 8 + 4];
            float4 u0 = *(const float4*)&Bs[buf][kk][tx * 8];
            float4 u1 = *(const float4*)&Bs[buf][kk][tx * 8 + 4];
            unsigned long long a2[8], b2[4];
            a2[0]=pk2(t0.x,t0.x); a2[1]=pk2(t0.y,t0.y);
            a2[2]=pk2(t0.z,t0.z); a2[3]=pk2(t0.w,t0.w);
            a2[4]=pk2(t1.x,t1.x); a2[5]=pk2(t1.y,t1.y);
            a2[6]=pk2(t1.z,t1.z); a2[7]=pk2(t1.w,t1.w);
            b2[0]=pk2(u0.x,u0.y); b2[1]=pk2(u0.z,u0.w);
            b2[2]=pk2(u1.x,u1.y); b2[3]=pk2(u1.z,u1.w);
#pragma unroll
            for (int i = 0; i < 8; i++)
#pragma unroll
                for (int j = 0; j < 4; j++)
                    FFMA2(acc[i][j], a2[i], b2[j]);
        }
        if (c + 1 < NK) {
            const int nb = (c + 1) & 1;
#pragma unroll
            for (int i = 0; i < 2; i++) {
                int lin = tid + 256 * i;
                int row = lin >> 2;
                int kq  = (lin & 3) * 4;
                As[nb][kq + 0][row] = pa[i].x; As[nb][kq + 1][row] = pa[i].y;
                As[nb][kq + 2][row] = pa[i].z; As[nb][kq + 3][row] = pa[i].w;
                Bs[nb][kq + 0][row] = pb[i].x; Bs[nb][kq + 1][row] = pb[i].y;
                Bs[nb][kq + 2][row] = pb[i].z; Bs[nb][kq + 3][row] = pb[i].w;
            }
        }
        __syncthreads();
    }

#pragma unroll
    for (int i = 0; i < 8; i++) {
        int gm = m0 + ty * 8 + i;
        if (gm >= MROWS) continue;
        int wdw = gm / NTOK, t = gm - wdw * NTOK;
#pragma unroll
        for (int jp = 0; jp < 4; jp++) {
            float v0, v1;
            upk2(acc[i][jp], v0, v1);
#pragma unroll
            for (int e = 0; e < 2; e++) {
                int gn = n0 + tx * 8 + jp * 2 + e;
                float cv = (e ? v1 : v0) + bias[gn];
                int which = gn / DIM_;
                int r = gn - which * DIM_;
                int h = r >> 6, d = r & 63;
                int idx = ((wdw * NH_ + h) * NTOK + t) * HD_ + d;
                float* dst = (which == 0) ? g_q : ((which == 1) ? g_k : g_v);
                dst[idx] = cv;
            }
        }
    }
}

// =====================================================================
// scores v3 (passing round-14 version)
// =====================================================================
#define SC_SMEM_FLOATS (8448 + 7424 + 8448)
#define SC_SMEM_BYTES  (SC_SMEM_FLOATS * 4)
#define NREL 27

__global__ __launch_bounds__(256)
void scores_gemm(const float* __restrict__ rph, const float* __restrict__ rpw)
{
    extern __shared__ float sm[];
    float* As  = sm;
    float* Th  = As + 8448;
    float* Tw  = Th + 3712;
    float* Bs  = Tw + 3712;
    float* tbl = Bs;

    const int tid = threadIdx.x;
    const int bh  = blockIdx.y;
    const int m0  = blockIdx.x * 128;
    const int tx  = tid & 15;
    const int ty  = tid >> 4;
    const float* Q = g_q + bh * (NTOK * HD_);
    const float* K = g_k + bh * (NTOK * HD_);

#pragma unroll
    for (int i = 0; i < 8; i++) {
        int e = tid + 256 * i;
        int row = e >> 4;
        int d0  = (e & 15) * 4;
        float4 v = make_float4(0.f, 0.f, 0.f, 0.f);
        if (m0 + row < NTOK) v = *(const float4*)(Q + (m0 + row) * HD_ + d0);
        As[(d0 + 0) * 132 + row] = v.x;
        As[(d0 + 1) * 132 + row] = v.y;
        As[(d0 + 2) * 132 + row] = v.z;
        As[(d0 + 3) * 132 + row] = v.w;
    }
    for (int i = tid; i < 2 * NREL * HD_; i += 256) {
        int isW = (i >= NREL * HD_);
        int l = isW ? i - NREL * HD_ : i;
        int r = l >> 6, d = l & 63;
        tbl[(isW ? 1755 : 0) + r * 65 + d] = __ldg((isW ? rpw : rph) + r * HD_ + d);
    }
    __syncthreads();

    {
        const int ty2 = tid >> 3;
        const int tx2 = tid & 7;
#pragma unroll
        for (int tb = 0; tb < 2; tb++) {
            const float* tb_base = tbl + (tb ? 1755 : 0);
            float* Tout = tb ? Tw : Th;
            float t[4][4];
#pragma unroll
            for (int i = 0; i < 4; i++)
#pragma unroll
                for (int j = 0; j < 4; j++) t[i][j] = 0.f;
#pragma unroll 8
            for (int d = 0; d < HD_; d++) {
                float qv[4], tv[4];
#pragma unroll
                for (int i = 0; i < 4; i++)
                    qv[i] = As[d * 132 + ty2 * 4 + i];
#pragma unroll
                for (int j = 0; j < 4; j++) {
                    int col = tx2 * 4 + j;
                    tv[j] = tb_base[(col < NREL ? col : 0) * 65 + d];
                }
#pragma unroll
                for (int i = 0; i < 4; i++)
#pragma unroll
                    for (int j = 0; j < 4; j++)
                        t[i][j] = fmaf(qv[i], tv[j], t[i][j]);
            }
#pragma unroll
            for (int j = 0; j < 4; j++) {
                int col = tx2 * 4 + j;
                if (col < NREL) {
#pragma unroll
                    for (int i = 0; i < 4; i++)
                        Tout[(ty2 * 4 + i) * 29 + col] = t[i][j];
                }
            }
        }
    }
    __syncthreads();

    for (int half = 0; half < 2; half++) {
        const int n0 = half * 128;
#pragma unroll
        for (int i = 0; i < 8; i++) {
            int e = tid + 256 * i;
            int row = e >> 4;
            int d0  = (e & 15) * 4;
            float4 v = make_float4(0.f, 0.f, 0.f, 0.f);
            if (n0 + row < NTOK) v = *(const float4*)(K + (n0 + row) * HD_ + d0);
            Bs[(d0 + 0) * 132 + row] = v.x;
            Bs[(d0 + 1) * 132 + row] = v.y;
            Bs[(d0 + 2) * 132 + row] = v.z;
            Bs[(d0 + 3) * 132 + row] = v.w;
        }
        __syncthreads();

        float acc[8][8];
#pragma unroll
        for (int i = 0; i < 8; i++)
#pragma unroll
            for (int j = 0; j < 8; j++) acc[i][j] = 0.f;

#pragma unroll 8
        for (int kk = 0; kk < HD_; kk++) {
            float a[8], b[8];
            float4 t0 = *(const float4*)&As[kk * 132 + ty * 8];
            float4 t1 = *(const float4*)&As[kk * 132 + ty * 8 + 4];
            a[0]=t0.x; a[1]=t0.y; a[2]=t0.z; a[3]=t0.w;
            a[4]=t1.x; a[5]=t1.y; a[6]=t1.z; a[7]=t1.w;
            float4 u0 = *(const float4*)&Bs[kk * 132 + tx * 8];
            float4 u1 = *(const float4*)&Bs[kk * 132 + tx * 8 + 4];
            b[0]=u0.x; b[1]=u0.y; b[2]=u0.z; b[3]=u0.w;
            b[4]=u1.x; b[5]=u1.y; b[6]=u1.z; b[7]=u1.w;
#pragma unroll
            for (int i = 0; i < 8; i++)
#pragma unroll
                for (int j = 0; j < 8; j++)
                    acc[i][j] = fmaf(a[i], b[j], acc[i][j]);
        }

        int khs[8], kws[8];
#pragma unroll
        for (int j = 0; j < 8; j++) {
            int gn = n0 + tx * 8 + j;
            int kh = gn / WS_;
            khs[j] = kh;
            kws[j] = gn - kh * WS_;
        }
#pragma unroll
        for (int i = 0; i < 8; i++) {
            int gm = m0 + ty * 8 + i;
            if (gm >= NTOK) continue;
            int lrow = ty * 8 + i;
            int qh  = gm / WS_;
            int qwc = gm - qh * WS_;
            float* srow = g_s + (size_t)bh * NN_ + gm * NTOK;
            const float* thr = Th + lrow * 29 + (qh + WS_ - 1);
            const float* twr = Tw + lrow * 29 + (qwc + WS_ - 1);
#pragma unroll
            for (int j = 0; j < 8; j++) {
                int gn = n0 + tx * 8 + j;
                if (gn >= NTOK) continue;
                srow[gn] = acc[i][j] * 0.125f + thr[-khs[j]] + twr[-kws[j]];
            }
        }
        __syncthreads();
    }
}

// =====================================================================
// softmax (passing version)
// =====================================================================
__global__ __launch_bounds__(128)
void softmax_kernel()
{
    const int lane = threadIdx.x & 31;
    const size_t row = (size_t)blockIdx.x * 4 + (threadIdx.x >> 5);
    float* s = g_s + row * NTOK;

    float v[7];
    float mx = -INFINITY;
#pragma unroll
    for (int t = 0; t < 7; t++) {
        int j = lane + 32 * t;
        v[t] = (j < NTOK) ? s[j] : -INFINITY;
        mx = fmaxf(mx, v[t]);
    }
#pragma unroll
    for (int off = 16; off > 0; off >>= 1)
        mx = fmaxf(mx, __shfl_xor_sync(0xffffffffu, mx, off));
    float sum = 0.f;
#pragma unroll
    for (int t = 0; t < 7; t++) {
        int j = lane + 32 * t;
        if (j < NTOK) {
            float e = __expf(v[t] - mx);
            v[t] = e;
            sum += e;
        }
    }
#pragma unroll
    for (int off = 16; off > 0; off >>= 1)
        sum += __shfl_xor_sync(0xffffffffu, sum, off);
    float inv = 1.f / sum;
#pragma unroll
    for (int t = 0; t < 7; t++) {
        int j = lane + 32 * t;
        if (j < NTOK) s[j] = v[t] * inv;
    }
}

// =====================================================================
// av v2 (passing round-14 version)
// =====================================================================
#define AV_SMEM_FLOATS (208 * 68 + 2 * 16 * 260)
#define AV_SMEM_BYTES  (AV_SMEM_FLOATS * 4)

__global__ __launch_bounds__(256)
void av_gemm()
{
    extern __shared__ float sm[];
    float* Vs = sm;
    float* Ab = Vs + 208 * 68;

    const int tid = threadIdx.x;
    const int bh  = blockIdx.x;
    const int tx  = tid & 7;
    const int ty  = tid >> 3;
    const float* P = g_s + (size_t)bh * NN_;
    const float* V = g_v + bh * (NTOK * HD_);
    const int wdw = bh / NH_, hh = bh - wdw * NH_;

    for (int i = tid; i < 208 * 16; i += 256) {
        int row = i >> 4;
        int c4  = (i & 15) * 4;
        float4 v = make_float4(0.f, 0.f, 0.f, 0.f);
        if (row < NTOK) v = *(const float4*)(V + row * HD_ + c4);
        *(float4*)&Vs[row * 68 + c4] = v;
    }

    float acc[8][8];
#pragma unroll
    for (int i = 0; i < 8; i++)
#pragma unroll
        for (int j = 0; j < 8; j++) acc[i][j] = 0.f;

    const int NC = 13;
    float4 pa[4];

#pragma unroll
    for (int i = 0; i < 4; i++) {
        int lin = tid + 256 * i;
        int row = lin >> 2;
        int kq  = (lin & 3) * 4;
        pa[i] = make_float4(0.f, 0.f, 0.f, 0.f);
        if (row < NTOK) pa[i] = *(const float4*)(P + row * NTOK + kq);
    }
#pragma unroll
    for (int i = 0; i < 4; i++) {
        int lin = tid + 256 * i;
        int row = lin >> 2;
        int kq  = (lin & 3) * 4;
        Ab[(kq + 0) * 260 + row] = pa[i].x;
        Ab[(kq + 1) * 260 + row] = pa[i].y;
        Ab[(kq + 2) * 260 + row] = pa[i].z;
        Ab[(kq + 3) * 260 + row] = pa[i].w;
    }
    __syncthreads();

    for (int c = 0; c < NC; c++) {
        if (c + 1 < NC) {
            int k0 = (c + 1) * 16;
#pragma unroll
            for (int i = 0; i < 4; i++) {
                int lin = tid + 256 * i;
                int row = lin >> 2;
                int kq  = (lin & 3) * 4;
                pa[i] = make_float4(0.f, 0.f, 0.f, 0.f);
                if (row < NTOK && (k0 + kq) < NTOK)
                    pa[i] = *(const float4*)(P + row * NTOK + k0 + kq);
            }
        }
        const float* Ac = Ab + (c & 1) * 4160;
        const float* Vc = Vs + c * 16 * 68;
#pragma unroll
        for (int kk = 0; kk < 16; kk++) {
            float a[8], b[8];
            float4 t0 = *(const float4*)&Ac[kk * 260 + ty * 8];
            float4 t1 = *(const float4*)&Ac[kk * 260 + ty * 8 + 4];
            a[0]=t0.x; a[1]=t0.y; a[2]=t0.z; a[3]=t0.w;
            a[4]=t1.x; a[5]=t1.y; a[6]=t1.z; a[7]=t1.w;
            float4 u0 = *(const float4*)&Vc[kk * 68 + tx * 8];
            float4 u1 = *(const float4*)&Vc[kk * 68 + tx * 8 + 4];
            b[0]=u0.x; b[1]=u0.y; b[2]=u0.z; b[3]=u0.w;
            b[4]=u1.x; b[5]=u1.y; b[6]=u1.z; b[7]=u1.w;
#pragma unroll
            for (int i = 0; i < 8; i++)
#pragma unroll
                for (int j = 0; j < 8; j++)
                    acc[i][j] = fmaf(a[i], b[j], acc[i][j]);
        }
        if (c + 1 < NC) {
            float* An = Ab + ((c + 1) & 1) * 4160;
#pragma unroll
            for (int i = 0; i < 4; i++) {
                int lin = tid + 256 * i;
                int row = lin >> 2;
                int kq  = (lin & 3) * 4;
                An[(kq + 0) * 260 + row] = pa[i].x;
                An[(kq + 1) * 260 + row] = pa[i].y;
                An[(kq + 2) * 260 + row] = pa[i].z;
                An[(kq + 3) * 260 + row] = pa[i].w;
            }
        }
        __syncthreads();
    }

#pragma unroll
    for (int i = 0; i < 8; i++) {
        int gm = ty * 8 + i;
        if (gm >= NTOK) continue;
        float* orow = g_ao + (size_t)(wdw * NTOK + gm) * DIM_ + hh * HD_ + tx * 8;
        *(float4*)orow       = make_float4(acc[i][0], acc[i][1], acc[i][2], acc[i][3]);
        *(float4*)(orow + 4) = make_float4(acc[i][4], acc[i][5], acc[i][6], acc[i][7]);
    }
}

// =====================================================================
// GEMM 2: out = g_ao @ proj_w^T + proj_b — f32x2 packed microkernel
// =====================================================================
__global__ __launch_bounds__(256)
void proj_gemm(const float* __restrict__ w, const float* __restrict__ bias,
               float* __restrict__ out)
{
    __shared__ float As[2][16][132];
    __shared__ float Bs[2][16][132];
    const int tid = threadIdx.x;
    const int m0 = blockIdx.x * 128;
    const int n0 = blockIdx.y * 128;
    const int tx = tid & 15;
    const int ty = tid >> 4;

    int abase[2];
#pragma unroll
    for (int i = 0; i < 2; i++) {
        int lin = tid + 256 * i;
        int row = lin >> 2;
        int gm  = m0 + row;
        abase[i] = (gm < MROWS) ? gm * DIM_ : -1;
    }

    unsigned long long acc[8][4];
#pragma unroll
    for (int i = 0; i < 8; i++)
#pragma unroll
        for (int j = 0; j < 4; j++) acc[i][j] = 0ULL;

    float4 pa[2], pb[2];
#pragma unroll
    for (int i = 0; i < 2; i++) {
        int lin = tid + 256 * i;
        int kq  = (lin & 3) * 4;
        pa[i] = make_float4(0.f, 0.f, 0.f, 0.f);
        if (abase[i] >= 0) pa[i] = *(const float4*)(g_ao + abase[i] + kq);
        int row = lin >> 2;
        pb[i] = *(const float4*)(w + (n0 + row) * DIM_ + kq);
    }
#pragma unroll
    for (int i = 0; i < 2; i++) {
        int lin = tid + 256 * i;
        int row = lin >> 2;
        int kq  = (lin & 3) * 4;
        As[0][kq + 0][row] = pa[i].x; As[0][kq + 1][row] = pa[i].y;
        As[0][kq + 2][row] = pa[i].z; As[0][kq + 3][row] = pa[i].w;
        Bs[0][kq + 0][row] = pb[i].x; Bs[0][kq + 1][row] = pb[i].y;
        Bs[0][kq + 2][row] = pb[i].z; Bs[0][kq + 3][row] = pb[i].w;
    }
    __syncthreads();

    const int NK = DIM_ / 16;
    for (int c = 0; c < NK; c++) {
        if (c + 1 < NK) {
            int k0 = (c + 1) * 16;
#pragma unroll
            for (int i = 0; i < 2; i++) {
                int lin = tid + 256 * i;
                int kq  = (lin & 3) * 4;
                pa[i] = make_float4(0.f, 0.f, 0.f, 0.f);
                if (abase[i] >= 0) pa[i] = *(const float4*)(g_ao + abase[i] + k0 + kq);
                int row = lin >> 2;
                pb[i] = *(const float4*)(w + (n0 + row) * DIM_ + k0 + kq);
            }
        }
        const int buf = c & 1;
#pragma unroll
        for (int kk = 0; kk < 16; kk++) {
            float4 t0 = *(const float4*)&As[buf][kk][ty * 8];
            float4 t1 = *(const float4*)&As[buf][kk][ty * 8 + 4];
            float4 u0 = *(const float4*)&Bs[buf][kk][tx * 8];
            float4 u1 = *(const float4*)&Bs[buf][kk][tx * 8 + 4];
            unsigned long long a2[8], b2[4];
            a2[0]=pk2(t0.x,t0.x); a2[1]=pk2(t0.y,t0.y);
            a2[2]=pk2(t0.z,t0.z); a2[3]=pk2(t0.w,t0.w);
            a2[4]=pk2(t1.x,t1.x); a2[5]=pk2(t1.y,t1.y);
            a2[6]=pk2(t1.z,t1.z); a2[7]=pk2(t1.w,t1.w);
            b2[0]=pk2(u0.x,u0.y); b2[1]=pk2(u0.z,u0.w);
            b2[2]=pk2(u1.x,u1.y); b2[3]=pk2(u1.z,u1.w);
#pragma unroll
            for (int i = 0; i < 8; i++)
#pragma unroll
                for (int j = 0; j < 4; j++)
                    FFMA2(acc[i][j], a2[i], b2[j]);
        }
        if (c + 1 < NK) {
            const int nb = (c + 1) & 1;
#pragma unroll
            for (int i = 0; i < 2; i++) {
                int lin = tid + 256 * i;
                int row = lin >> 2;
                int kq  = (lin & 3) * 4;
                As[nb][kq + 0][row] = pa[i].x; As[nb][kq + 1][row] = pa[i].y;
                As[nb][kq + 2][row] = pa[i].z; As[nb][kq + 3][row] = pa[i].w;
                Bs[nb][kq + 0][row] = pb[i].x; Bs[nb][kq + 1][row] = pb[i].y;
                Bs[nb][kq + 2][row] = pb[i].z; Bs[nb][kq + 3][row] = pb[i].w;
            }
        }
        __syncthreads();
    }

#pragma unroll
    for (int i = 0; i < 8; i++) {
        int gm = m0 + ty * 8 + i;
        if (gm >= MROWS) continue;
        int wdw = gm / NTOK, t = gm - wdw * NTOK;
        int b  = wdw / 25,  wi = wdw - b * 25;
        int wh = wi / 5,    ww = wi - wh * 5;
        int th = t / WS_,   tw = t - th * WS_;
        int y  = wh * WS_ + th;
        int xc = ww * WS_ + tw;
        if (y >= IMGHW || xc >= IMGHW) continue;
        float* orow = out + ((b * IMGHW + y) * IMGHW + xc) * DIM_;
#pragma unroll
        for (int jp = 0; jp < 4; jp++) {
            float v0, v1;
            upk2(acc[i][jp], v0, v1);
            int gn = n0 + tx * 8 + jp * 2;
            orow[gn]     = v0 + bias[gn];
            orow[gn + 1] = v1 + bias[gn + 1];
        }
    }
}

// =====================================================================
extern "C" void kernel_launch(void* const* d_in, const int* in_sizes, int n_in,
                              void* d_out, int out_size)
{
    const float* x      = (const float*)d_in[0];
    const float* qkv_w  = (const float*)d_in[1];
    const float* qkv_b  = (const float*)d_in[2];
    const float* proj_w = (const float*)d_in[3];
    const float* proj_b = (const float*)d_in[4];
    const float* rph    = (const float*)d_in[5];
    const float* rpw    = (const float*)d_in[6];
    float* out = (float*)d_out;

    cudaFuncSetAttribute(scores_gemm,
                         cudaFuncAttributeMaxDynamicSharedMemorySize, SC_SMEM_BYTES);
    cudaFuncSetAttribute(av_gemm,
                         cudaFuncAttributeMaxDynamicSharedMemorySize, AV_SMEM_BYTES);

    dim3 g1((MROWS + 127) / 128, QKV_N / 128);
    qkv_gemm<<<g1, 256>>>(x, qkv_w, qkv_b);

    dim3 gs(2, BH_);
    scores_gemm<<<gs, 256, SC_SMEM_BYTES>>>(rph, rpw);

    softmax_kernel<<<(BH_ * NTOK) / 4, 128>>>();

    av_gemm<<<BH_, 256, AV_SMEM_BYTES>>>();

    dim3 g2((MROWS + 127) / 128, DIM_ / 128);
    proj_gemm<<<g2, 256>>>(proj_w, proj_b, out);
}